// round 1
// baseline (speedup 1.0000x reference)
#include <cuda_runtime.h>
#include <cstdint>

#define DN 128          // feature dim (all layers)
#define N_MAX 100000

// Scratch (allocation-free rule: __device__ globals)
__device__ float g_dinv[N_MAX];                       // deg -> dinv (in place)
__device__ float g_buf1[(size_t)N_MAX * DN];          // h1, then h2
__device__ float g_buf2[(size_t)N_MAX * DN];          // agg1 (relu input to layer 2)

// ---------------------------------------------------------------------------
// Degree: deg[i] = 1 (self loop) + count of edges with col == i, then rsqrt.
// ---------------------------------------------------------------------------
__global__ void k_init_deg(float* __restrict__ deg, int n) {
    int i = blockIdx.x * blockDim.x + threadIdx.x;
    if (i < n) deg[i] = 1.0f;
}

__global__ void k_count_deg(const int* __restrict__ col, float* __restrict__ deg, int e) {
    int i = blockIdx.x * blockDim.x + threadIdx.x;
    if (i < e) atomicAdd(&deg[col[i]], 1.0f);
}

__global__ void k_rsqrt(float* __restrict__ deg, int n) {
    int i = blockIdx.x * blockDim.x + threadIdx.x;
    if (i < n) deg[i] = rsqrtf(deg[i]);
}

// ---------------------------------------------------------------------------
// GEMM: C[n,128] = act(A[n,128]) @ W[128,128]
// Block: 256 threads, 64 rows/block. A tile in smem (32 KB), W streamed from
// L1/L2 (W is 64 KB, chip-resident). Warp w computes rows w*8..w*8+7; lane
// computes a float4 of output columns. 8x4 accumulators per thread.
// RELU applies to the *input* A (used for layer 2: relu(agg1) @ W2).
// ---------------------------------------------------------------------------
template <bool RELU>
__global__ void k_gemm(const float* __restrict__ A, const float* __restrict__ W,
                       float* __restrict__ C, int n) {
    __shared__ float As[64][DN];
    const int tid = threadIdx.x;
    const int block_row = blockIdx.x * 64;

    // Load A tile: 64*128 floats = 2048 float4, 8 per thread.
#pragma unroll
    for (int i = 0; i < 8; i++) {
        int f = tid + i * 256;        // float4 index within tile
        int r = f >> 5;               // 32 float4 per row
        int c4 = f & 31;
        int gr = block_row + r;
        float4 v = make_float4(0.f, 0.f, 0.f, 0.f);
        if (gr < n)
            v = reinterpret_cast<const float4*>(A)[(size_t)gr * 32 + c4];
        if (RELU) {
            v.x = fmaxf(v.x, 0.f); v.y = fmaxf(v.y, 0.f);
            v.z = fmaxf(v.z, 0.f); v.w = fmaxf(v.w, 0.f);
        }
        reinterpret_cast<float4*>(&As[r][0])[c4] = v;
    }
    __syncthreads();

    const int warp = tid >> 5;
    const int lane = tid & 31;
    float4 acc[8];
#pragma unroll
    for (int r = 0; r < 8; r++) acc[r] = make_float4(0.f, 0.f, 0.f, 0.f);

    const float4* W4 = reinterpret_cast<const float4*>(W);
#pragma unroll 4
    for (int k = 0; k < DN; k++) {
        float4 w = __ldg(&W4[k * 32 + lane]);   // W row-major [k][out]
#pragma unroll
        for (int r = 0; r < 8; r++) {
            float a = As[warp * 8 + r][k];      // smem broadcast across lanes
            acc[r].x = fmaf(a, w.x, acc[r].x);
            acc[r].y = fmaf(a, w.y, acc[r].y);
            acc[r].z = fmaf(a, w.z, acc[r].z);
            acc[r].w = fmaf(a, w.w, acc[r].w);
        }
    }

#pragma unroll
    for (int r = 0; r < 8; r++) {
        int gr = block_row + warp * 8 + r;
        if (gr < n)
            reinterpret_cast<float4*>(C)[(size_t)gr * 32 + lane] = acc[r];
    }
}

// ---------------------------------------------------------------------------
// Self-loop + bias init: out[i][d] = dinv[i]^2 * h[i][d] + b[d]
// (Fully overwrites out — required since d_out is poisoned.)
// ---------------------------------------------------------------------------
__global__ void k_self_loop(const float* __restrict__ h, const float* __restrict__ dinv,
                            const float* __restrict__ b, float* __restrict__ out, int n) {
    size_t idx = (size_t)blockIdx.x * blockDim.x + threadIdx.x;  // float4 idx
    size_t total = (size_t)n * 32;
    if (idx >= total) return;
    int node = (int)(idx >> 5);
    int c4 = (int)(idx & 31);
    float di = dinv[node];
    float s = di * di;
    float4 hv = reinterpret_cast<const float4*>(h)[idx];
    float4 bv = reinterpret_cast<const float4*>(b)[c4];
    float4 o;
    o.x = fmaf(s, hv.x, bv.x);
    o.y = fmaf(s, hv.y, bv.y);
    o.z = fmaf(s, hv.z, bv.z);
    o.w = fmaf(s, hv.w, bv.w);
    reinterpret_cast<float4*>(out)[idx] = o;
}

// ---------------------------------------------------------------------------
// Edge scatter: for each edge (r -> c):
//   out[c][:] += dinv[r]*dinv[c] * h[r][:]
// One warp per edge; lane handles one float4 of the 128-dim feature.
// Gather from h is coalesced (512B/warp, L2-resident). Accumulate with
// vector reduction (red.global.add.v4.f32, resolved at L2 atomic ALUs).
// ---------------------------------------------------------------------------
__global__ void k_scatter(const float* __restrict__ h, const float* __restrict__ dinv,
                          const int* __restrict__ rowv, const int* __restrict__ colv,
                          float* __restrict__ out, int e) {
    int gid = blockIdx.x * blockDim.x + threadIdx.x;
    int edge = gid >> 5;
    if (edge >= e) return;
    int lane = gid & 31;
    int r = __ldg(&rowv[edge]);   // warp-uniform (broadcast)
    int c = __ldg(&colv[edge]);
    float coef = __ldg(&dinv[r]) * __ldg(&dinv[c]);
    float4 hv = __ldg(&reinterpret_cast<const float4*>(h)[(size_t)r * 32 + lane]);
    float4 v;
    v.x = coef * hv.x; v.y = coef * hv.y; v.z = coef * hv.z; v.w = coef * hv.w;
    float* p = out + (size_t)c * DN + lane * 4;
    asm volatile("red.global.add.v4.f32 [%0], {%1, %2, %3, %4};"
                 :: "l"(p), "f"(v.x), "f"(v.y), "f"(v.z), "f"(v.w)
                 : "memory");
}

// ---------------------------------------------------------------------------
extern "C" void kernel_launch(void* const* d_in, const int* in_sizes, int n_in,
                              void* d_out, int out_size) {
    const float* x   = (const float*)d_in[0];   // [N,128]
    const int*   ei  = (const int*)d_in[1];     // [2,E]
    const float* W1  = (const float*)d_in[2];   // [128,128]
    const float* b1  = (const float*)d_in[3];   // [128]
    const float* W2  = (const float*)d_in[4];   // [128,128]
    const float* b2  = (const float*)d_in[5];   // [128]
    float* out = (float*)d_out;

    const int n = in_sizes[0] / DN;
    const int e = in_sizes[1] / 2;
    const int* rowv = ei;
    const int* colv = ei + e;

    float *dinv, *buf1, *buf2;
    cudaGetSymbolAddress((void**)&dinv, g_dinv);
    cudaGetSymbolAddress((void**)&buf1, g_buf1);
    cudaGetSymbolAddress((void**)&buf2, g_buf2);

    const int T = 256;
    // 1) degree / dinv
    k_init_deg<<<(n + T - 1) / T, T>>>(dinv, n);
    k_count_deg<<<(e + T - 1) / T, T>>>(colv, dinv, e);
    k_rsqrt<<<(n + T - 1) / T, T>>>(dinv, n);

    const int gemm_blocks = (n + 63) / 64;
    const size_t nd4 = (size_t)n * 32;                       // float4 elements
    const int sl_blocks = (int)((nd4 + T - 1) / T);
    const long long scatter_threads = (long long)e * 32;
    const int sc_blocks = (int)((scatter_threads + T - 1) / T);

    // 2) layer 1: h1 = x @ W1
    k_gemm<false><<<gemm_blocks, T>>>(x, W1, buf1, n);
    // 3) agg1 = dinv^2 * h1 + b1, then scatter edges
    k_self_loop<<<sl_blocks, T>>>(buf1, dinv, b1, buf2, n);
    k_scatter<<<sc_blocks, T>>>(buf1, dinv, rowv, colv, buf2, e);

    // 4) layer 2: h2 = relu(agg1) @ W2
    k_gemm<true><<<gemm_blocks, T>>>(buf2, W2, buf1, n);
    // 5) out = dinv^2 * h2 + b2, then scatter edges into d_out
    k_self_loop<<<sl_blocks, T>>>(buf1, dinv, b2, out, n);
    k_scatter<<<sc_blocks, T>>>(buf1, dinv, rowv, colv, out, e);
}

// round 2
// speedup vs baseline: 2.0847x; 2.0847x over previous
#include <cuda_runtime.h>
#include <cstdint>

#define DN 128
#define N_MAX 100000
#define E_MAX 2000000

// Scratch (allocation-free rule: __device__ globals)
__device__ int   g_degi[N_MAX];
__device__ int   g_part[N_MAX];          // per-block exclusive scan partials
__device__ int   g_bsums[512];           // block sums (<=512 blocks of 256)
__device__ int   g_rowstart[N_MAX + 1];  // CSR offsets (by target node)
__device__ int   g_cursor[N_MAX];        // fill cursors
__device__ int   g_csr[E_MAX];           // source node per CSR slot
__device__ float g_dinv[N_MAX];
__device__ float g_buf1[(size_t)N_MAX * DN];
__device__ float g_buf2[(size_t)N_MAX * DN];

// ---------------------------------------------------------------------------
// Degree + CSR build (by target/col node)
// ---------------------------------------------------------------------------
__global__ void k_zero_deg(int* __restrict__ deg, int n) {
    int i = blockIdx.x * blockDim.x + threadIdx.x;
    if (i < n) deg[i] = 0;
}

__global__ void k_count_deg(const int* __restrict__ col, int* __restrict__ deg, int e) {
    int i = blockIdx.x * blockDim.x + threadIdx.x;
    if (i < e) atomicAdd(&deg[col[i]], 1);
}

// Per-block exclusive scan; emits block totals.
__global__ void k_scan1(const int* __restrict__ deg, int* __restrict__ part,
                        int* __restrict__ bsums, int n) {
    __shared__ int sh[256];
    int t = threadIdx.x;
    int i = blockIdx.x * 256 + t;
    int v = (i < n) ? deg[i] : 0;
    sh[t] = v;
    __syncthreads();
#pragma unroll
    for (int off = 1; off < 256; off <<= 1) {
        int add = (t >= off) ? sh[t - off] : 0;
        __syncthreads();
        sh[t] += add;
        __syncthreads();
    }
    if (i < n) part[i] = sh[t] - v;   // exclusive
    if (t == 255) bsums[blockIdx.x] = sh[255];
}

// Single-block exclusive scan of block sums (nb <= 512).
__global__ void k_scan2(int* __restrict__ bsums, int nb) {
    __shared__ int sh[512];
    int t = threadIdx.x;
    int v = (t < nb) ? bsums[t] : 0;
    sh[t] = v;
    __syncthreads();
#pragma unroll
    for (int off = 1; off < 512; off <<= 1) {
        int add = (t >= off) ? sh[t - off] : 0;
        __syncthreads();
        sh[t] += add;
        __syncthreads();
    }
    if (t < nb) bsums[t] = sh[t] - v;  // exclusive
}

__global__ void k_scan3(const int* __restrict__ part, const int* __restrict__ bsums,
                        int* __restrict__ rowstart, int* __restrict__ cursor,
                        int n, int e) {
    int i = blockIdx.x * blockDim.x + threadIdx.x;
    if (i < n) {
        int v = part[i] + bsums[blockIdx.x * 256 / 256 == 0 ? 0 : 0];  // placeholder; fixed below
    }
    // (re-derive block index from i to keep launch geometry free)
    if (i < n) {
        int v = part[i] + bsums[i >> 8];
        rowstart[i] = v;
        cursor[i] = v;
    }
    if (i == 0) rowstart[n] = e;
}

__global__ void k_fill(const int* __restrict__ rowv, const int* __restrict__ colv,
                       int* __restrict__ cursor, int* __restrict__ csr, int e) {
    int i = blockIdx.x * blockDim.x + threadIdx.x;
    if (i < e) {
        int pos = atomicAdd(&cursor[colv[i]], 1);
        csr[pos] = rowv[i];
    }
}

__global__ void k_dinv(const int* __restrict__ deg, float* __restrict__ dinv, int n) {
    int i = blockIdx.x * blockDim.x + threadIdx.x;
    if (i < n) dinv[i] = rsqrtf((float)deg[i] + 1.0f);
}

// ---------------------------------------------------------------------------
// GEMM: C[i,:] = dinv[i] * (act(A[i,:]) @ W)    (h' = dinv-scaled projection)
// 256 threads, 64 rows/block. A tile in smem. Inner loop steps k by 4:
// broadcast LDS.128 for A, LDG.128 for W (L1-resident), 128 FFMA per step.
// ---------------------------------------------------------------------------
template <bool RELU>
__global__ void __launch_bounds__(256)
k_gemm(const float* __restrict__ A, const float* __restrict__ W,
       const float* __restrict__ dinv, float* __restrict__ C, int n) {
    __shared__ float As[64 * DN];
    const int tid = threadIdx.x;
    const int block_row = blockIdx.x * 64;

#pragma unroll
    for (int i = 0; i < 8; i++) {
        int f = tid + i * 256;
        int r = f >> 5;
        int c4 = f & 31;
        int gr = block_row + r;
        float4 v = make_float4(0.f, 0.f, 0.f, 0.f);
        if (gr < n)
            v = reinterpret_cast<const float4*>(A)[(size_t)gr * 32 + c4];
        if (RELU) {
            v.x = fmaxf(v.x, 0.f); v.y = fmaxf(v.y, 0.f);
            v.z = fmaxf(v.z, 0.f); v.w = fmaxf(v.w, 0.f);
        }
        reinterpret_cast<float4*>(As)[r * 32 + c4] = v;
    }
    __syncthreads();

    const int warp = tid >> 5;
    const int lane = tid & 31;
    float4 acc[8];
#pragma unroll
    for (int r = 0; r < 8; r++) acc[r] = make_float4(0.f, 0.f, 0.f, 0.f);

    const float4* W4 = reinterpret_cast<const float4*>(W);
    const float4* As4 = reinterpret_cast<const float4*>(As);

    for (int k4 = 0; k4 < 32; k4++) {
        float4 w0 = __ldg(&W4[(4 * k4 + 0) * 32 + lane]);
        float4 w1 = __ldg(&W4[(4 * k4 + 1) * 32 + lane]);
        float4 w2 = __ldg(&W4[(4 * k4 + 2) * 32 + lane]);
        float4 w3 = __ldg(&W4[(4 * k4 + 3) * 32 + lane]);
#pragma unroll
        for (int r = 0; r < 8; r++) {
            float4 a = As4[(warp * 8 + r) * 32 + k4];   // broadcast, conflict-free
            acc[r].x = fmaf(a.x, w0.x, acc[r].x);
            acc[r].y = fmaf(a.x, w0.y, acc[r].y);
            acc[r].z = fmaf(a.x, w0.z, acc[r].z);
            acc[r].w = fmaf(a.x, w0.w, acc[r].w);
            acc[r].x = fmaf(a.y, w1.x, acc[r].x);
            acc[r].y = fmaf(a.y, w1.y, acc[r].y);
            acc[r].z = fmaf(a.y, w1.z, acc[r].z);
            acc[r].w = fmaf(a.y, w1.w, acc[r].w);
            acc[r].x = fmaf(a.z, w2.x, acc[r].x);
            acc[r].y = fmaf(a.z, w2.y, acc[r].y);
            acc[r].z = fmaf(a.z, w2.z, acc[r].z);
            acc[r].w = fmaf(a.z, w2.w, acc[r].w);
            acc[r].x = fmaf(a.w, w3.x, acc[r].x);
            acc[r].y = fmaf(a.w, w3.y, acc[r].y);
            acc[r].z = fmaf(a.w, w3.z, acc[r].z);
            acc[r].w = fmaf(a.w, w3.w, acc[r].w);
        }
    }

#pragma unroll
    for (int r = 0; r < 8; r++) {
        int gr = block_row + warp * 8 + r;
        if (gr < n) {
            float s = __ldg(&dinv[gr]);
            float4 o;
            o.x = s * acc[r].x; o.y = s * acc[r].y;
            o.z = s * acc[r].z; o.w = s * acc[r].w;
            reinterpret_cast<float4*>(C)[(size_t)gr * 32 + lane] = o;
        }
    }
}

// ---------------------------------------------------------------------------
// Gather aggregation (no atomics): warp per target node c.
//   out[c] = dinv[c] * (h'[c] + sum_{r in in(c)} h'[r]) + b
// h' already carries the source-side dinv scale.
// ---------------------------------------------------------------------------
__global__ void __launch_bounds__(256)
k_gather(const float* __restrict__ h, const float* __restrict__ dinv,
         const int* __restrict__ rowstart, const int* __restrict__ csr,
         const float* __restrict__ b, float* __restrict__ out, int n) {
    int gid = blockIdx.x * blockDim.x + threadIdx.x;
    int node = gid >> 5;
    if (node >= n) return;
    int lane = gid & 31;

    const float4* h4 = reinterpret_cast<const float4*>(h);
    float4 acc = __ldg(&h4[(size_t)node * 32 + lane]);   // self term (h' scaled)

    int s = __ldg(&rowstart[node]);
    int t = __ldg(&rowstart[node + 1]);
#pragma unroll 4
    for (int j = s; j < t; j++) {
        int r = __ldg(&csr[j]);                          // warp-broadcast
        float4 v = __ldg(&h4[(size_t)r * 32 + lane]);    // coalesced 512B/warp
        acc.x += v.x; acc.y += v.y; acc.z += v.z; acc.w += v.w;
    }

    float dc = __ldg(&dinv[node]);
    float4 bv = reinterpret_cast<const float4*>(b)[lane];
    float4 o;
    o.x = fmaf(dc, acc.x, bv.x);
    o.y = fmaf(dc, acc.y, bv.y);
    o.z = fmaf(dc, acc.z, bv.z);
    o.w = fmaf(dc, acc.w, bv.w);
    reinterpret_cast<float4*>(out)[(size_t)node * 32 + lane] = o;
}

// ---------------------------------------------------------------------------
extern "C" void kernel_launch(void* const* d_in, const int* in_sizes, int n_in,
                              void* d_out, int out_size) {
    const float* x  = (const float*)d_in[0];
    const int*   ei = (const int*)d_in[1];
    const float* W1 = (const float*)d_in[2];
    const float* b1 = (const float*)d_in[3];
    const float* W2 = (const float*)d_in[4];
    const float* b2 = (const float*)d_in[5];
    float* out = (float*)d_out;

    const int n = in_sizes[0] / DN;
    const int e = in_sizes[1] / 2;
    const int* rowv = ei;
    const int* colv = ei + e;

    int *degi, *part, *bsums, *rowstart, *cursor, *csr;
    float *dinv, *buf1, *buf2;
    cudaGetSymbolAddress((void**)&degi, g_degi);
    cudaGetSymbolAddress((void**)&part, g_part);
    cudaGetSymbolAddress((void**)&bsums, g_bsums);
    cudaGetSymbolAddress((void**)&rowstart, g_rowstart);
    cudaGetSymbolAddress((void**)&cursor, g_cursor);
    cudaGetSymbolAddress((void**)&csr, g_csr);
    cudaGetSymbolAddress((void**)&dinv, g_dinv);
    cudaGetSymbolAddress((void**)&buf1, g_buf1);
    cudaGetSymbolAddress((void**)&buf2, g_buf2);

    const int T = 256;
    const int nb = (n + T - 1) / T;       // scan blocks (391 for N=100K)
    const int eb = (e + T - 1) / T;

    // CSR build + dinv
    k_zero_deg<<<nb, T>>>(degi, n);
    k_count_deg<<<eb, T>>>(colv, degi, e);
    k_scan1<<<nb, T>>>(degi, part, bsums, n);
    k_scan2<<<1, 512>>>(bsums, nb);
    k_scan3<<<nb, T>>>(part, bsums, rowstart, cursor, n, e);
    k_fill<<<eb, T>>>(rowv, colv, cursor, csr, e);
    k_dinv<<<nb, T>>>(degi, dinv, n);

    const int gemm_blocks = (n + 63) / 64;
    const int gather_blocks = (int)(((long long)n * 32 + T - 1) / T);

    // Layer 1
    k_gemm<false><<<gemm_blocks, T>>>(x, W1, dinv, buf1, n);
    k_gather<<<gather_blocks, T>>>(buf1, dinv, rowstart, csr, b1, buf2, n);
    // Layer 2
    k_gemm<true><<<gemm_blocks, T>>>(buf2, W2, dinv, buf1, n);
    k_gather<<<gather_blocks, T>>>(buf1, dinv, rowstart, csr, b2, out, n);
}

// round 5
// speedup vs baseline: 2.3496x; 1.1271x over previous
#include <cuda_runtime.h>
#include <cuda_bf16.h>
#include <cstdint>

#define DN 128
#define N_MAX 100000
#define E_MAX 2000000
#define BPAD 136                 // padded bf16 row stride (ldmatrix conflict-free)

// ---------------------------------------------------------------------------
// Scratch (__device__ globals; no allocation allowed)
// ---------------------------------------------------------------------------
__device__ int   g_degi[N_MAX];
__device__ int   g_part[N_MAX];
__device__ int   g_bsums[512];
__device__ int   g_rowstart[N_MAX + 1];
__device__ int   g_cursor[N_MAX];
__device__ int   g_csr[E_MAX];
__device__ float g_dinv[N_MAX];
__device__ float g_buf1[(size_t)N_MAX * DN];
__device__ float g_buf2[(size_t)N_MAX * DN];
// Pre-split B operands, padded [n][BPAD] bf16 (B[n][k] = W[k][n])
__device__ __align__(16) __nv_bfloat16 g_B1hi[DN * BPAD];
__device__ __align__(16) __nv_bfloat16 g_B1lo[DN * BPAD];
__device__ __align__(16) __nv_bfloat16 g_B2hi[DN * BPAD];
__device__ __align__(16) __nv_bfloat16 g_B2lo[DN * BPAD];

__device__ __forceinline__ uint32_t smem_to_u32(const void* p) {
    uint32_t addr;
    asm("{ .reg .u64 tmp; cvta.to.shared.u64 tmp, %1; cvt.u32.u64 %0, tmp; }"
        : "=r"(addr) : "l"(p));
    return addr;
}

#define LDMATRIX_X4(r, addr) \
    asm volatile("ldmatrix.sync.aligned.m8n8.x4.shared.b16 {%0,%1,%2,%3}, [%4];" \
                 : "=r"((r)[0]), "=r"((r)[1]), "=r"((r)[2]), "=r"((r)[3]) \
                 : "r"(addr))

#define MMA_BF16(d, a, b0, b1) \
    asm volatile("mma.sync.aligned.m16n8k16.row.col.f32.bf16.bf16.f32 " \
                 "{%0,%1,%2,%3}, {%4,%5,%6,%7}, {%8,%9}, {%0,%1,%2,%3};" \
                 : "+f"((d)[0]), "+f"((d)[1]), "+f"((d)[2]), "+f"((d)[3]) \
                 : "r"((a)[0]), "r"((a)[1]), "r"((a)[2]), "r"((a)[3]), \
                   "r"(b0), "r"(b1))

// ---------------------------------------------------------------------------
// CSR build (by target/col node) + dinv
// ---------------------------------------------------------------------------
__global__ void k_zero_deg(int* __restrict__ deg, int n) {
    int i = blockIdx.x * blockDim.x + threadIdx.x;
    if (i < n) deg[i] = 0;
}

__global__ void k_count_deg(const int* __restrict__ col, int* __restrict__ deg, int e) {
    int i = blockIdx.x * blockDim.x + threadIdx.x;
    if (i < e) atomicAdd(&deg[col[i]], 1);
}

__global__ void k_scan1(const int* __restrict__ deg, int* __restrict__ part,
                        int* __restrict__ bsums, int n) {
    __shared__ int sh[256];
    int t = threadIdx.x;
    int i = blockIdx.x * 256 + t;
    int v = (i < n) ? deg[i] : 0;
    sh[t] = v;
    __syncthreads();
#pragma unroll
    for (int off = 1; off < 256; off <<= 1) {
        int add = (t >= off) ? sh[t - off] : 0;
        __syncthreads();
        sh[t] += add;
        __syncthreads();
    }
    if (i < n) part[i] = sh[t] - v;
    if (t == 255) bsums[blockIdx.x] = sh[255];
}

__global__ void k_scan2(int* __restrict__ bsums, int nb) {
    __shared__ int sh[512];
    int t = threadIdx.x;
    int v = (t < nb) ? bsums[t] : 0;
    sh[t] = v;
    __syncthreads();
#pragma unroll
    for (int off = 1; off < 512; off <<= 1) {
        int add = (t >= off) ? sh[t - off] : 0;
        __syncthreads();
        sh[t] += add;
        __syncthreads();
    }
    if (t < nb) bsums[t] = sh[t] - v;
}

__global__ void k_scan3(const int* __restrict__ part, const int* __restrict__ bsums,
                        const int* __restrict__ deg, float* __restrict__ dinv,
                        int* __restrict__ rowstart, int* __restrict__ cursor,
                        int n, int e) {
    int i = blockIdx.x * blockDim.x + threadIdx.x;
    if (i < n) {
        int v = part[i] + bsums[i >> 8];
        rowstart[i] = v;
        cursor[i] = v;
        dinv[i] = rsqrtf((float)deg[i] + 1.0f);
    }
    if (i == 0) rowstart[n] = e;
}

__global__ void k_fill(const int* __restrict__ rowv, const int* __restrict__ colv,
                       int* __restrict__ cursor, int* __restrict__ csr, int e) {
    int i = blockIdx.x * blockDim.x + threadIdx.x;
    if (i < e) {
        int pos = atomicAdd(&cursor[colv[i]], 1);
        csr[pos] = rowv[i];
    }
}

// ---------------------------------------------------------------------------
// W split: B[n][k] = W[k][n] -> bf16 hi/lo, padded [n][BPAD]
// ---------------------------------------------------------------------------
__global__ void k_wsplit(const float* __restrict__ W,
                         __nv_bfloat16* __restrict__ Bhi,
                         __nv_bfloat16* __restrict__ Blo) {
    int i = blockIdx.x * blockDim.x + threadIdx.x;
    if (i >= DN * DN) return;
    int nrow = i & 127;                 // coalesced read of W row
    int k = i >> 7;
    float w = W[k * DN + nrow];
    __nv_bfloat16 hi = __float2bfloat16_rn(w);
    __nv_bfloat16 lo = __float2bfloat16_rn(w - __bfloat162float(hi));
    Bhi[nrow * BPAD + k] = hi;
    Blo[nrow * BPAD + k] = lo;
}

// ---------------------------------------------------------------------------
// mma.sync GEMM: C[i,:] = dinv[i] * (act(A[i,:]) @ W), 3-MMA bf16 split.
// CTA: 256 thr (8 warps, 4(m) x 2(n)), tile 128x128x128. 1 CTA/SM.
// ---------------------------------------------------------------------------
#define SM_AHI 0
#define SM_ALO (SM_AHI + DN * BPAD * 2)      // 34816
#define SM_BHI (SM_ALO + DN * BPAD * 2)      // 69632
#define SM_BLO (SM_BHI + DN * BPAD * 2)      // 104448
#define SM_GEMM_TOTAL (SM_BLO + DN * BPAD * 2)  // 139264
#define STG_STRIDE 132                        // fp32 staging row stride

template <bool RELU>
__global__ void __launch_bounds__(256, 1)
k_gemm_mma(const float* __restrict__ A, const __nv_bfloat16* __restrict__ Bhi,
           const __nv_bfloat16* __restrict__ Blo, const float* __restrict__ dinv,
           float* __restrict__ C, int n) {
    extern __shared__ __align__(16) char smem[];
    const uint32_t sbase = smem_to_u32(smem);
    const int tid = threadIdx.x;
    const int wid = tid >> 5;
    const int lane = tid & 31;
    const int wm = wid & 3;            // warp row: 32 rows
    const int wn = wid >> 2;           // warp col: 64 cols
    const int block_row = blockIdx.x * 128;

    // --- B copy (pre-split, padded): 2x 34816 B straight memcpy ---
    {
        const uint4* srcH = reinterpret_cast<const uint4*>(Bhi);
        const uint4* srcL = reinterpret_cast<const uint4*>(Blo);
        uint4* dstH = reinterpret_cast<uint4*>(smem + SM_BHI);
        uint4* dstL = reinterpret_cast<uint4*>(smem + SM_BLO);
#pragma unroll
        for (int i = 0; i < 9; i++) {
            int f = tid + i * 256;               // 2176 uint4 per tile
            if (f < DN * BPAD / 8) {
                dstH[f] = __ldg(&srcH[f]);
                dstL[f] = __ldg(&srcL[f]);
            }
        }
    }

    // --- A convert: fp32 -> bf16 hi/lo into padded smem rows ---
    {
        const float4* A4 = reinterpret_cast<const float4*>(A);
        __nv_bfloat16* Ah = reinterpret_cast<__nv_bfloat16*>(smem + SM_AHI);
        __nv_bfloat16* Al = reinterpret_cast<__nv_bfloat16*>(smem + SM_ALO);
#pragma unroll
        for (int i = 0; i < 16; i++) {
            int f = tid + i * 256;               // 4096 float4
            int r = f >> 5;
            int c4 = f & 31;
            int gr = block_row + r;
            float4 v = make_float4(0.f, 0.f, 0.f, 0.f);
            if (gr < n) v = __ldg(&A4[(size_t)gr * 32 + c4]);
            if (RELU) {
                v.x = fmaxf(v.x, 0.f); v.y = fmaxf(v.y, 0.f);
                v.z = fmaxf(v.z, 0.f); v.w = fmaxf(v.w, 0.f);
            }
            __nv_bfloat162 h01 = __floats2bfloat162_rn(v.x, v.y);
            __nv_bfloat162 h23 = __floats2bfloat162_rn(v.z, v.w);
            float lx = v.x - __bfloat162float(h01.x);
            float ly = v.y - __bfloat162float(h01.y);
            float lz = v.z - __bfloat162float(h23.x);
            float lw = v.w - __bfloat162float(h23.y);
            __nv_bfloat162 l01 = __floats2bfloat162_rn(lx, ly);
            __nv_bfloat162 l23 = __floats2bfloat162_rn(lz, lw);
            int idx = r * BPAD + c4 * 4;
            *reinterpret_cast<uint2*>(&Ah[idx]) =
                make_uint2(*reinterpret_cast<uint32_t*>(&h01),
                           *reinterpret_cast<uint32_t*>(&h23));
            *reinterpret_cast<uint2*>(&Al[idx]) =
                make_uint2(*reinterpret_cast<uint32_t*>(&l01),
                           *reinterpret_cast<uint32_t*>(&l23));
        }
    }
    __syncthreads();

    // --- Main loop: 8 k-steps of 16 ---
    float acc[2][8][4];
#pragma unroll
    for (int im = 0; im < 2; im++)
#pragma unroll
        for (int jn = 0; jn < 8; jn++)
#pragma unroll
            for (int q = 0; q < 4; q++) acc[im][jn][q] = 0.f;

    // ldmatrix lane addressing: row = base + lane%16, col byte = (k0 + (lane/16)*8)*2
    const int lrow = lane & 15;
    const int lcol = (lane >> 4) << 3;

#pragma unroll
    for (int ks = 0; ks < 8; ks++) {
        const int k0 = ks * 16;
        uint32_t ah[2][4], al[2][4], bh[4][4], bl[4][4];
#pragma unroll
        for (int im = 0; im < 2; im++) {
            uint32_t off = (uint32_t)(((wm * 32 + im * 16 + lrow) * BPAD + k0 + lcol) * 2);
            LDMATRIX_X4(ah[im], sbase + SM_AHI + off);
            LDMATRIX_X4(al[im], sbase + SM_ALO + off);
        }
#pragma unroll
        for (int jg = 0; jg < 4; jg++) {
            uint32_t off = (uint32_t)(((wn * 64 + jg * 16 + lrow) * BPAD + k0 + lcol) * 2);
            LDMATRIX_X4(bh[jg], sbase + SM_BHI + off);
            LDMATRIX_X4(bl[jg], sbase + SM_BLO + off);
        }
#pragma unroll
        for (int im = 0; im < 2; im++) {
#pragma unroll
            for (int jg = 0; jg < 4; jg++) {
                // n8 tile jg*2   -> regs {r0, r2};  tile jg*2+1 -> {r1, r3}
                MMA_BF16(acc[im][jg * 2], ah[im], bh[jg][0], bh[jg][2]);
                MMA_BF16(acc[im][jg * 2 + 1], ah[im], bh[jg][1], bh[jg][3]);
                MMA_BF16(acc[im][jg * 2], ah[im], bl[jg][0], bl[jg][2]);
                MMA_BF16(acc[im][jg * 2 + 1], ah[im], bl[jg][1], bl[jg][3]);
                MMA_BF16(acc[im][jg * 2], al[im], bh[jg][0], bh[jg][2]);
                MMA_BF16(acc[im][jg * 2 + 1], al[im], bh[jg][1], bh[jg][3]);
            }
        }
    }
    __syncthreads();     // all warps done reading smem; reuse as fp32 staging

    // --- Epilogue: stage fp32, then coalesced dinv-scaled store ---
    {
        float* stage = reinterpret_cast<float*>(smem);    // 128 x STG_STRIDE
        const int trow = lane >> 2;
        const int tcol = (lane & 3) * 2;
#pragma unroll
        for (int im = 0; im < 2; im++) {
#pragma unroll
            for (int jn = 0; jn < 8; jn++) {
                int r0 = wm * 32 + im * 16 + trow;
                int c = wn * 64 + jn * 8 + tcol;
                stage[r0 * STG_STRIDE + c]     = acc[im][jn][0];
                stage[r0 * STG_STRIDE + c + 1] = acc[im][jn][1];
                stage[(r0 + 8) * STG_STRIDE + c]     = acc[im][jn][2];
                stage[(r0 + 8) * STG_STRIDE + c + 1] = acc[im][jn][3];
            }
        }
        __syncthreads();
        float4* C4 = reinterpret_cast<float4*>(C);
#pragma unroll
        for (int i = 0; i < 16; i++) {
            int f = tid + i * 256;
            int r = f >> 5;
            int c4 = f & 31;
            int gr = block_row + r;
            if (gr < n) {
                float s = __ldg(&dinv[gr]);
                const float* sp = &stage[r * STG_STRIDE + c4 * 4];
                float4 o = make_float4(s * sp[0], s * sp[1], s * sp[2], s * sp[3]);
                C4[(size_t)gr * 32 + c4] = o;
            }
        }
    }
}

// ---------------------------------------------------------------------------
// Gather aggregation (no atomics): warp per target node c.
//   out[c] = dinv[c] * (h'[c] + sum_{r in in(c)} h'[r]) + b
// ---------------------------------------------------------------------------
__global__ void __launch_bounds__(256)
k_gather(const float* __restrict__ h, const float* __restrict__ dinv,
         const int* __restrict__ rowstart, const int* __restrict__ csr,
         const float* __restrict__ b, float* __restrict__ out, int n) {
    int gid = blockIdx.x * blockDim.x + threadIdx.x;
    int node = gid >> 5;
    if (node >= n) return;
    int lane = gid & 31;

    const float4* h4 = reinterpret_cast<const float4*>(h);
    float4 acc = __ldg(&h4[(size_t)node * 32 + lane]);

    int s = __ldg(&rowstart[node]);
    int t = __ldg(&rowstart[node + 1]);
#pragma unroll 4
    for (int j = s; j < t; j++) {
        int r = __ldg(&csr[j]);
        float4 v = __ldg(&h4[(size_t)r * 32 + lane]);
        acc.x += v.x; acc.y += v.y; acc.z += v.z; acc.w += v.w;
    }

    float dc = __ldg(&dinv[node]);
    float4 bv = reinterpret_cast<const float4*>(b)[lane];
    float4 o;
    o.x = fmaf(dc, acc.x, bv.x);
    o.y = fmaf(dc, acc.y, bv.y);
    o.z = fmaf(dc, acc.z, bv.z);
    o.w = fmaf(dc, acc.w, bv.w);
    reinterpret_cast<float4*>(out)[(size_t)node * 32 + lane] = o;
}

// ---------------------------------------------------------------------------
extern "C" void kernel_launch(void* const* d_in, const int* in_sizes, int n_in,
                              void* d_out, int out_size) {
    const float* x  = (const float*)d_in[0];
    const int*   ei = (const int*)d_in[1];
    const float* W1 = (const float*)d_in[2];
    const float* b1 = (const float*)d_in[3];
    const float* W2 = (const float*)d_in[4];
    const float* b2 = (const float*)d_in[5];
    float* out = (float*)d_out;

    const int n = in_sizes[0] / DN;
    const int e = in_sizes[1] / 2;
    const int* rowv = ei;
    const int* colv = ei + e;

    int *degi, *part, *bsums, *rowstart, *cursor, *csr;
    float *dinv, *buf1, *buf2;
    __nv_bfloat16 *B1hi, *B1lo, *B2hi, *B2lo;
    cudaGetSymbolAddress((void**)&degi, g_degi);
    cudaGetSymbolAddress((void**)&part, g_part);
    cudaGetSymbolAddress((void**)&bsums, g_bsums);
    cudaGetSymbolAddress((void**)&rowstart, g_rowstart);
    cudaGetSymbolAddress((void**)&cursor, g_cursor);
    cudaGetSymbolAddress((void**)&csr, g_csr);
    cudaGetSymbolAddress((void**)&dinv, g_dinv);
    cudaGetSymbolAddress((void**)&buf1, g_buf1);
    cudaGetSymbolAddress((void**)&buf2, g_buf2);
    cudaGetSymbolAddress((void**)&B1hi, g_B1hi);
    cudaGetSymbolAddress((void**)&B1lo, g_B1lo);
    cudaGetSymbolAddress((void**)&B2hi, g_B2hi);
    cudaGetSymbolAddress((void**)&B2lo, g_B2lo);

    cudaFuncSetAttribute(k_gemm_mma<false>,
                         cudaFuncAttributeMaxDynamicSharedMemorySize, SM_GEMM_TOTAL);
    cudaFuncSetAttribute(k_gemm_mma<true>,
                         cudaFuncAttributeMaxDynamicSharedMemorySize, SM_GEMM_TOTAL);

    const int T = 256;
    const int nb = (n + T - 1) / T;
    const int eb = (e + T - 1) / T;

    // W splits (independent of everything else)
    k_wsplit<<<(DN * DN + T - 1) / T, T>>>(W1, B1hi, B1lo);
    k_wsplit<<<(DN * DN + T - 1) / T, T>>>(W2, B2hi, B2lo);

    // CSR build + dinv
    k_zero_deg<<<nb, T>>>(degi, n);
    k_count_deg<<<eb, T>>>(colv, degi, e);
    k_scan1<<<nb, T>>>(degi, part, bsums, n);
    k_scan2<<<1, 512>>>(bsums, nb);
    k_scan3<<<nb, T>>>(part, bsums, degi, dinv, rowstart, cursor, n, e);
    k_fill<<<eb, T>>>(rowv, colv, cursor, csr, e);

    const int gemm_blocks = (n + 127) / 128;
    const int gather_blocks = (int)(((long long)n * 32 + T - 1) / T);

    // Layer 1
    k_gemm_mma<false><<<gemm_blocks, T, SM_GEMM_TOTAL>>>(x, B1hi, B1lo, dinv, buf1, n);
    k_gather<<<gather_blocks, T>>>(buf1, dinv, rowstart, csr, b1, buf2, n);
    // Layer 2
    k_gemm_mma<true><<<gemm_blocks, T, SM_GEMM_TOTAL>>>(buf2, B2hi, B2lo, dinv, buf1, n);
    k_gather<<<gather_blocks, T>>>(buf1, dinv, rowstart, csr, b2, out, n);
}

// round 7
// speedup vs baseline: 2.5093x; 1.0679x over previous
#include <cuda_runtime.h>
#include <cuda_bf16.h>
#include <cstdint>

#define DN 128
#define N_MAX 100000
#define E_MAX 2000000
#define BPAD 136                 // padded bf16 row stride (ldmatrix conflict-free)

// ---------------------------------------------------------------------------
// Scratch (__device__ globals; no allocation allowed)
// ---------------------------------------------------------------------------
__device__ int   g_degi[N_MAX];
__device__ int   g_part[N_MAX];
__device__ int   g_bsums[512];
__device__ int   g_rowstart[N_MAX + 1];
__device__ int   g_cursor[N_MAX];
__device__ int   g_csr[E_MAX];
__device__ float g_dinv[N_MAX];
__device__ float g_buf1[(size_t)N_MAX * DN];
__device__ float g_buf2[(size_t)N_MAX * DN];
__device__ __align__(16) __nv_bfloat16 g_B1hi[DN * BPAD];
__device__ __align__(16) __nv_bfloat16 g_B1lo[DN * BPAD];
__device__ __align__(16) __nv_bfloat16 g_B2hi[DN * BPAD];
__device__ __align__(16) __nv_bfloat16 g_B2lo[DN * BPAD];

__device__ __forceinline__ uint32_t smem_to_u32(const void* p) {
    uint32_t addr;
    asm("{ .reg .u64 tmp; cvta.to.shared.u64 tmp, %1; cvt.u32.u64 %0, tmp; }"
        : "=r"(addr) : "l"(p));
    return addr;
}

#define LDMATRIX_X4(r, addr) \
    asm volatile("ldmatrix.sync.aligned.m8n8.x4.shared.b16 {%0,%1,%2,%3}, [%4];" \
                 : "=r"((r)[0]), "=r"((r)[1]), "=r"((r)[2]), "=r"((r)[3]) \
                 : "r"(addr))

#define MMA_BF16(d, a, b0, b1) \
    asm volatile("mma.sync.aligned.m16n8k16.row.col.f32.bf16.bf16.f32 " \
                 "{%0,%1,%2,%3}, {%4,%5,%6,%7}, {%8,%9}, {%0,%1,%2,%3};" \
                 : "+f"((d)[0]), "+f"((d)[1]), "+f"((d)[2]), "+f"((d)[3]) \
                 : "r"((a)[0]), "r"((a)[1]), "r"((a)[2]), "r"((a)[3]), \
                   "r"(b0), "r"(b1))

// fp32 pair -> bf16x2 hi + bf16x2 lo (error-free-ish split)
__device__ __forceinline__ void split2(float2 f, uint32_t& hi, uint32_t& lo) {
    __nv_bfloat162 h = __floats2bfloat162_rn(f.x, f.y);
    float rx = f.x - __bfloat162float(h.x);
    float ry = f.y - __bfloat162float(h.y);
    __nv_bfloat162 l = __floats2bfloat162_rn(rx, ry);
    hi = *reinterpret_cast<uint32_t*>(&h);
    lo = *reinterpret_cast<uint32_t*>(&l);
}

// ---------------------------------------------------------------------------
// CSR build (by target/col node) + dinv
// ---------------------------------------------------------------------------
__global__ void k_count_deg(const int* __restrict__ col, int* __restrict__ deg, int e) {
    int i = blockIdx.x * blockDim.x + threadIdx.x;
    int base = i * 4;
    if (base + 3 < e) {
        int4 c = *reinterpret_cast<const int4*>(col + base);
        atomicAdd(&deg[c.x], 1);
        atomicAdd(&deg[c.y], 1);
        atomicAdd(&deg[c.z], 1);
        atomicAdd(&deg[c.w], 1);
    } else {
        for (int j = base; j < e; j++) atomicAdd(&deg[col[j]], 1);
    }
}

__global__ void k_scan1(const int* __restrict__ deg, int* __restrict__ part,
                        int* __restrict__ bsums, int n) {
    __shared__ int sh[256];
    int t = threadIdx.x;
    int i = blockIdx.x * 256 + t;
    int v = (i < n) ? deg[i] : 0;
    sh[t] = v;
    __syncthreads();
#pragma unroll
    for (int off = 1; off < 256; off <<= 1) {
        int add = (t >= off) ? sh[t - off] : 0;
        __syncthreads();
        sh[t] += add;
        __syncthreads();
    }
    if (i < n) part[i] = sh[t] - v;
    if (t == 255) bsums[blockIdx.x] = sh[255];
}

// scan of bsums folded in: each block reduces bsums[0..bid) itself.
__global__ void k_scan3(const int* __restrict__ part, const int* __restrict__ bsums,
                        const int* __restrict__ deg, float* __restrict__ dinv,
                        int* __restrict__ rowstart, int* __restrict__ cursor,
                        int n, int e) {
    __shared__ int sred[256];
    int t = threadIdx.x;
    int accum = 0;
    for (int j = t; j < (int)blockIdx.x; j += 256) accum += bsums[j];
    sred[t] = accum;
    __syncthreads();
#pragma unroll
    for (int off = 128; off > 0; off >>= 1) {
        if (t < off) sred[t] += sred[t + off];
        __syncthreads();
    }
    int base = sred[0];

    int i = blockIdx.x * 256 + t;
    if (i < n) {
        int v = part[i] + base;
        rowstart[i] = v;
        cursor[i] = v;
        dinv[i] = rsqrtf((float)deg[i] + 1.0f);
    }
    if (i == 0 && blockIdx.x == 0) {
        // rowstart[n]: total edges
        rowstart[n] = e;
    }
}

__global__ void k_fill(const int* __restrict__ rowv, const int* __restrict__ colv,
                       int* __restrict__ cursor, int* __restrict__ csr, int e) {
    int i = blockIdx.x * blockDim.x + threadIdx.x;
    if (i < e) {
        int pos = atomicAdd(&cursor[colv[i]], 1);
        csr[pos] = rowv[i];
    }
}

// ---------------------------------------------------------------------------
// W split: B[n][k] = W[k][n] -> bf16 hi/lo, padded [n][BPAD]
// ---------------------------------------------------------------------------
__global__ void k_wsplit(const float* __restrict__ W,
                         __nv_bfloat16* __restrict__ Bhi,
                         __nv_bfloat16* __restrict__ Blo) {
    int i = blockIdx.x * blockDim.x + threadIdx.x;
    if (i >= DN * DN) return;
    int nrow = i & 127;
    int k = i >> 7;
    float w = W[k * DN + nrow];
    __nv_bfloat16 hi = __float2bfloat16_rn(w);
    __nv_bfloat16 lo = __float2bfloat16_rn(w - __bfloat162float(hi));
    Bhi[nrow * BPAD + k] = hi;
    Blo[nrow * BPAD + k] = lo;
}

// ---------------------------------------------------------------------------
// mma.sync GEMM: C = act(A) @ W (unscaled), 3-MMA bf16 split.
// 256 thr = 8 warps; warp w owns rows [w*16, w*16+16) x ALL 128 cols.
// A fragments loaded DIRECTLY from global (fp32) and split in registers —
// no A smem stage. Smem = B hi/lo only (68 KB) -> 2 CTAs/SM.
// ---------------------------------------------------------------------------
#define SMB_HI 0
#define SMB_LO (DN * BPAD * 2)                 // 34816
#define SM_GEMM_TOTAL (2 * DN * BPAD * 2)      // 69632
#define STG_STRIDE 132

template <bool RELU>
__global__ void __launch_bounds__(256, 2)
k_gemm_mma(const float* __restrict__ A, const __nv_bfloat16* __restrict__ Bhi,
           const __nv_bfloat16* __restrict__ Blo, float* __restrict__ C, int n) {
    extern __shared__ __align__(16) char smem[];
    const uint32_t sbase = smem_to_u32(smem);
    const int tid = threadIdx.x;
    const int wid = tid >> 5;
    const int lane = tid & 31;
    const int block_row = blockIdx.x * 128;

    // --- B copy (pre-split, padded): 2 x 34816 B ---
    {
        const uint4* srcH = reinterpret_cast<const uint4*>(Bhi);
        const uint4* srcL = reinterpret_cast<const uint4*>(Blo);
        uint4* dstH = reinterpret_cast<uint4*>(smem + SMB_HI);
        uint4* dstL = reinterpret_cast<uint4*>(smem + SMB_LO);
#pragma unroll
        for (int i = 0; i < 9; i++) {
            int f = tid + i * 256;
            if (f < DN * BPAD / 8) {
                dstH[f] = __ldg(&srcH[f]);
                dstL[f] = __ldg(&srcL[f]);
            }
        }
    }

    // A fragment row pointers (fixed across k-steps)
    const int r0 = block_row + wid * 16 + (lane >> 2);
    const int r1 = r0 + 8;
    const bool p0 = r0 < n;
    const bool p1 = r1 < n;
    const float* A0 = A + (size_t)r0 * DN + (lane & 3) * 2;
    const float* A1 = A + (size_t)r1 * DN + (lane & 3) * 2;

    __syncthreads();

    float acc[16][4];
#pragma unroll
    for (int jn = 0; jn < 16; jn++)
#pragma unroll
        for (int q = 0; q < 4; q++) acc[jn][q] = 0.f;

    const int lrow = lane & 15;
    const int lcol = (lane >> 4) << 3;
    const float2 fz = make_float2(0.f, 0.f);

#pragma unroll
    for (int ks = 0; ks < 8; ks++) {
        const int k0 = ks * 16;
        // A fragment: 4 float2 direct global loads + register split
        float2 f00 = p0 ? *reinterpret_cast<const float2*>(A0 + k0) : fz;
        float2 f10 = p1 ? *reinterpret_cast<const float2*>(A1 + k0) : fz;
        float2 f01 = p0 ? *reinterpret_cast<const float2*>(A0 + k0 + 8) : fz;
        float2 f11 = p1 ? *reinterpret_cast<const float2*>(A1 + k0 + 8) : fz;
        if (RELU) {
            f00.x = fmaxf(f00.x, 0.f); f00.y = fmaxf(f00.y, 0.f);
            f10.x = fmaxf(f10.x, 0.f); f10.y = fmaxf(f10.y, 0.f);
            f01.x = fmaxf(f01.x, 0.f); f01.y = fmaxf(f01.y, 0.f);
            f11.x = fmaxf(f11.x, 0.f); f11.y = fmaxf(f11.y, 0.f);
        }
        uint32_t ah[4], al[4];
        split2(f00, ah[0], al[0]);
        split2(f10, ah[1], al[1]);
        split2(f01, ah[2], al[2]);
        split2(f11, ah[3], al[3]);

#pragma unroll
        for (int jg = 0; jg < 8; jg++) {
            uint32_t bh[4], bl[4];
            uint32_t off = (uint32_t)(((jg * 16 + lrow) * BPAD + k0 + lcol) * 2);
            LDMATRIX_X4(bh, sbase + SMB_HI + off);
            LDMATRIX_X4(bl, sbase + SMB_LO + off);
            MMA_BF16(acc[jg * 2],     ah, bh[0], bh[2]);
            MMA_BF16(acc[jg * 2 + 1], ah, bh[1], bh[3]);
            MMA_BF16(acc[jg * 2],     ah, bl[0], bl[2]);
            MMA_BF16(acc[jg * 2 + 1], ah, bl[1], bl[3]);
            MMA_BF16(acc[jg * 2],     al, bh[0], bh[2]);
            MMA_BF16(acc[jg * 2 + 1], al, bh[1], bh[3]);
        }
    }
    __syncthreads();     // done reading B smem; reuse as fp32 staging

    // --- Epilogue: stage fp32, coalesced store ---
    {
        float* stage = reinterpret_cast<float*>(smem);   // 128 x STG_STRIDE fp32
        const int trow = lane >> 2;
        const int tcol = (lane & 3) * 2;
#pragma unroll
        for (int jn = 0; jn < 16; jn++) {
            int rr = wid * 16 + trow;
            int c = jn * 8 + tcol;
            stage[rr * STG_STRIDE + c]     = acc[jn][0];
            stage[rr * STG_STRIDE + c + 1] = acc[jn][1];
            stage[(rr + 8) * STG_STRIDE + c]     = acc[jn][2];
            stage[(rr + 8) * STG_STRIDE + c + 1] = acc[jn][3];
        }
        __syncthreads();
        float4* C4 = reinterpret_cast<float4*>(C);
#pragma unroll
        for (int i = 0; i < 16; i++) {
            int f = tid + i * 256;
            int r = f >> 5;
            int c4 = f & 31;
            int gr = block_row + r;
            if (gr < n) {
                const float* sp = &stage[r * STG_STRIDE + c4 * 4];
                C4[(size_t)gr * 32 + c4] = make_float4(sp[0], sp[1], sp[2], sp[3]);
            }
        }
    }
}

// ---------------------------------------------------------------------------
// Gather (no atomics): warp per target node c, h UNSCALED:
//   out[c] = dinv[c] * ( dinv[c]*h[c] + sum_r dinv[r]*h[r] ) + b
// ---------------------------------------------------------------------------
__global__ void __launch_bounds__(256)
k_gather(const float* __restrict__ h, const float* __restrict__ dinv,
         const int* __restrict__ rowstart, const int* __restrict__ csr,
         const float* __restrict__ b, float* __restrict__ out, int n) {
    int gid = blockIdx.x * blockDim.x + threadIdx.x;
    int node = gid >> 5;
    if (node >= n) return;
    int lane = gid & 31;

    const float4* h4 = reinterpret_cast<const float4*>(h);
    float dc = __ldg(&dinv[node]);
    float4 self = __ldg(&h4[(size_t)node * 32 + lane]);
    float4 acc;
    acc.x = dc * self.x; acc.y = dc * self.y;
    acc.z = dc * self.z; acc.w = dc * self.w;

    int s = __ldg(&rowstart[node]);
    int t = __ldg(&rowstart[node + 1]);
#pragma unroll 4
    for (int j = s; j < t; j++) {
        int r = __ldg(&csr[j]);
        float dr = __ldg(&dinv[r]);
        float4 v = __ldg(&h4[(size_t)r * 32 + lane]);
        acc.x = fmaf(dr, v.x, acc.x);
        acc.y = fmaf(dr, v.y, acc.y);
        acc.z = fmaf(dr, v.z, acc.z);
        acc.w = fmaf(dr, v.w, acc.w);
    }

    float4 bv = reinterpret_cast<const float4*>(b)[lane];
    float4 o;
    o.x = fmaf(dc, acc.x, bv.x);
    o.y = fmaf(dc, acc.y, bv.y);
    o.z = fmaf(dc, acc.z, bv.z);
    o.w = fmaf(dc, acc.w, bv.w);
    reinterpret_cast<float4*>(out)[(size_t)node * 32 + lane] = o;
}

// ---------------------------------------------------------------------------
extern "C" void kernel_launch(void* const* d_in, const int* in_sizes, int n_in,
                              void* d_out, int out_size) {
    const float* x  = (const float*)d_in[0];
    const int*   ei = (const int*)d_in[1];
    const float* W1 = (const float*)d_in[2];
    const float* b1 = (const float*)d_in[3];
    const float* W2 = (const float*)d_in[4];
    const float* b2 = (const float*)d_in[5];
    float* out = (float*)d_out;

    const int n = in_sizes[0] / DN;
    const int e = in_sizes[1] / 2;
    const int* rowv = ei;
    const int* colv = ei + e;

    int *degi, *part, *bsums, *rowstart, *cursor, *csr;
    float *dinv, *buf1, *buf2;
    __nv_bfloat16 *B1hi, *B1lo, *B2hi, *B2lo;
    cudaGetSymbolAddress((void**)&degi, g_degi);
    cudaGetSymbolAddress((void**)&part, g_part);
    cudaGetSymbolAddress((void**)&bsums, g_bsums);
    cudaGetSymbolAddress((void**)&rowstart, g_rowstart);
    cudaGetSymbolAddress((void**)&cursor, g_cursor);
    cudaGetSymbolAddress((void**)&csr, g_csr);
    cudaGetSymbolAddress((void**)&dinv, g_dinv);
    cudaGetSymbolAddress((void**)&buf1, g_buf1);
    cudaGetSymbolAddress((void**)&buf2, g_buf2);
    cudaGetSymbolAddress((void**)&B1hi, g_B1hi);
    cudaGetSymbolAddress((void**)&B1lo, g_B1lo);
    cudaGetSymbolAddress((void**)&B2hi, g_B2hi);
    cudaGetSymbolAddress((void**)&B2lo, g_B2lo);

    cudaFuncSetAttribute(k_gemm_mma<false>,
                         cudaFuncAttributeMaxDynamicSharedMemorySize, SM_GEMM_TOTAL);
    cudaFuncSetAttribute(k_gemm_mma<true>,
                         cudaFuncAttributeMaxDynamicSharedMemorySize, SM_GEMM_TOTAL);

    const int T = 256;
    const int nb = (n + T - 1) / T;
    const int eb = (e + T - 1) / T;
    const int eb4 = ((e + 3) / 4 + T - 1) / T;

    // W splits
    k_wsplit<<<(DN * DN + T - 1) / T, T>>>(W1, B1hi, B1lo);
    k_wsplit<<<(DN * DN + T - 1) / T, T>>>(W2, B2hi, B2lo);

    // CSR build + dinv (single stream)
    cudaMemsetAsync(degi, 0, n * sizeof(int));
    k_count_deg<<<eb4, T>>>(colv, degi, e);
    k_scan1<<<nb, T>>>(degi, part, bsums, n);
    k_scan3<<<nb, T>>>(part, bsums, degi, dinv, rowstart, cursor, n, e);
    k_fill<<<eb, T>>>(rowv, colv, cursor, csr, e);

    const int gemm_blocks = (n + 127) / 128;
    const int gather_blocks = (int)(((long long)n * 32 + T - 1) / T);

    // Layer 1
    k_gemm_mma<false><<<gemm_blocks, T, SM_GEMM_TOTAL>>>(x, B1hi, B1lo, buf1, n);
    k_gather<<<gather_blocks, T>>>(buf1, dinv, rowstart, csr, b1, buf2, n);
    // Layer 2
    k_gemm_mma<true><<<gemm_blocks, T, SM_GEMM_TOTAL>>>(buf2, B2hi, B2lo, buf1, n);
    k_gather<<<gather_blocks, T>>>(buf1, dinv, rowstart, csr, b2, out, n);
}

// round 8
// speedup vs baseline: 2.6152x; 1.0422x over previous
#include <cuda_runtime.h>
#include <cuda_fp16.h>
#include <cstdint>

#define DN 128
#define N_MAX 100000
#define E_MAX 2000000
#define BPAD 136                 // padded fp16 row stride (ldmatrix conflict-free)

// ---------------------------------------------------------------------------
// Scratch (__device__ globals; no allocation allowed)
// ---------------------------------------------------------------------------
__device__ int   g_degi[N_MAX];
__device__ int   g_part[N_MAX];
__device__ int   g_bsums[512];
__device__ int   g_rowstart[N_MAX + 1];
__device__ int   g_cursor[N_MAX];
__device__ int   g_csr[E_MAX];
__device__ float g_dinv[N_MAX];
__device__ float g_buf1[(size_t)N_MAX * DN];
__device__ float g_buf2[(size_t)N_MAX * DN];
// W transposed+split: B[n][k] = W[k][n], exact fp16 2-term (hi + lo)
__device__ __align__(16) __half g_Bhi[2][DN * BPAD];   // [layer][...]
__device__ __align__(16) __half g_Blo[2][DN * BPAD];

__device__ __forceinline__ uint32_t smem_to_u32(const void* p) {
    uint32_t addr;
    asm("{ .reg .u64 tmp; cvta.to.shared.u64 tmp, %1; cvt.u32.u64 %0, tmp; }"
        : "=r"(addr) : "l"(p));
    return addr;
}

#define LDMATRIX_X4(r, addr) \
    asm volatile("ldmatrix.sync.aligned.m8n8.x4.shared.b16 {%0,%1,%2,%3}, [%4];" \
                 : "=r"((r)[0]), "=r"((r)[1]), "=r"((r)[2]), "=r"((r)[3]) \
                 : "r"(addr))

#define MMA_F16(d, a, b0, b1) \
    asm volatile("mma.sync.aligned.m16n8k16.row.col.f32.f16.f16.f32 " \
                 "{%0,%1,%2,%3}, {%4,%5,%6,%7}, {%8,%9}, {%0,%1,%2,%3};" \
                 : "+f"((d)[0]), "+f"((d)[1]), "+f"((d)[2]), "+f"((d)[3]) \
                 : "r"((a)[0]), "r"((a)[1]), "r"((a)[2]), "r"((a)[3]), \
                   "r"(b0), "r"(b1))

// ---------------------------------------------------------------------------
// CSR build (by target/col node) + dinv
// ---------------------------------------------------------------------------
__global__ void k_count_deg(const int* __restrict__ col, int* __restrict__ deg, int e) {
    int i = blockIdx.x * blockDim.x + threadIdx.x;
    int base = i * 4;
    if (base + 3 < e) {
        int4 c = *reinterpret_cast<const int4*>(col + base);
        atomicAdd(&deg[c.x], 1);
        atomicAdd(&deg[c.y], 1);
        atomicAdd(&deg[c.z], 1);
        atomicAdd(&deg[c.w], 1);
    } else {
        for (int j = base; j < e; j++) atomicAdd(&deg[col[j]], 1);
    }
}

__global__ void k_scan1(const int* __restrict__ deg, int* __restrict__ part,
                        int* __restrict__ bsums, int n) {
    __shared__ int sh[256];
    int t = threadIdx.x;
    int i = blockIdx.x * 256 + t;
    int v = (i < n) ? deg[i] : 0;
    sh[t] = v;
    __syncthreads();
#pragma unroll
    for (int off = 1; off < 256; off <<= 1) {
        int add = (t >= off) ? sh[t - off] : 0;
        __syncthreads();
        sh[t] += add;
        __syncthreads();
    }
    if (i < n) part[i] = sh[t] - v;
    if (t == 255) bsums[blockIdx.x] = sh[255];
}

// scan of bsums folded in: each block reduces bsums[0..bid) itself.
__global__ void k_scan3(const int* __restrict__ part, const int* __restrict__ bsums,
                        const int* __restrict__ deg, float* __restrict__ dinv,
                        int* __restrict__ rowstart, int* __restrict__ cursor,
                        int n, int e) {
    __shared__ int sred[256];
    int t = threadIdx.x;
    int accum = 0;
    for (int j = t; j < (int)blockIdx.x; j += 256) accum += bsums[j];
    sred[t] = accum;
    __syncthreads();
#pragma unroll
    for (int off = 128; off > 0; off >>= 1) {
        if (t < off) sred[t] += sred[t + off];
        __syncthreads();
    }
    int base = sred[0];

    int i = blockIdx.x * 256 + t;
    if (i < n) {
        int v = part[i] + base;
        rowstart[i] = v;
        cursor[i] = v;
        dinv[i] = rsqrtf((float)deg[i] + 1.0f);
    }
    if (i == 0 && blockIdx.x == 0) rowstart[n] = e;
}

__global__ void k_fill(const int* __restrict__ rowv, const int* __restrict__ colv,
                       int* __restrict__ cursor, int* __restrict__ csr, int e) {
    int i = blockIdx.x * blockDim.x + threadIdx.x;
    if (i < e) {
        int pos = atomicAdd(&cursor[colv[i]], 1);
        csr[pos] = rowv[i];
    }
}

// ---------------------------------------------------------------------------
// W split (both layers, one launch): B[n][k] = W[k][n] -> exact fp16 hi/lo
// ---------------------------------------------------------------------------
__global__ void k_wsplit(const float* __restrict__ W1, const float* __restrict__ W2,
                         __half* __restrict__ Bhi, __half* __restrict__ Blo) {
    int gi = blockIdx.x * blockDim.x + threadIdx.x;   // 2 * 16384
    if (gi >= 2 * DN * DN) return;
    int layer = gi >> 14;
    int i = gi & (DN * DN - 1);
    const float* W = layer ? W2 : W1;
    int nrow = i & 127;
    int k = i >> 7;
    float w = W[k * DN + nrow];
    __half hi = __float2half_rn(w);
    __half lo = __float2half_rn(w - __half2float(hi));
    Bhi[layer * DN * BPAD + nrow * BPAD + k] = hi;
    Blo[layer * DN * BPAD + nrow * BPAD + k] = lo;
}

// ---------------------------------------------------------------------------
// mma.sync GEMM: C = act(A) @ W (unscaled), fp16 2-term W split.
// 256 thr = 8 warps; warp w owns rows [w*16, w*16+16) x ALL 128 cols.
// A loaded directly from global, single fp16 rounding. Smem = B hi/lo (68 KB)
// -> 2 CTAs/SM.
// ---------------------------------------------------------------------------
#define SMB_HI 0
#define SMB_LO (DN * BPAD * 2)                 // 34816
#define SM_GEMM_TOTAL (2 * DN * BPAD * 2)      // 69632
#define STG_STRIDE 132

template <bool RELU>
__global__ void __launch_bounds__(256, 2)
k_gemm_mma(const float* __restrict__ A, const __half* __restrict__ Bhi,
           const __half* __restrict__ Blo, float* __restrict__ C, int n) {
    extern __shared__ __align__(16) char smem[];
    const uint32_t sbase = smem_to_u32(smem);
    const int tid = threadIdx.x;
    const int wid = tid >> 5;
    const int lane = tid & 31;
    const int block_row = blockIdx.x * 128;

    // --- B copy (pre-split, padded): 2 x 34816 B ---
    {
        const uint4* srcH = reinterpret_cast<const uint4*>(Bhi);
        const uint4* srcL = reinterpret_cast<const uint4*>(Blo);
        uint4* dstH = reinterpret_cast<uint4*>(smem + SMB_HI);
        uint4* dstL = reinterpret_cast<uint4*>(smem + SMB_LO);
#pragma unroll
        for (int i = 0; i < 9; i++) {
            int f = tid + i * 256;
            if (f < DN * BPAD / 8) {
                dstH[f] = __ldg(&srcH[f]);
                dstL[f] = __ldg(&srcL[f]);
            }
        }
    }

    // A fragment row pointers (fixed across k-steps)
    const int r0 = block_row + wid * 16 + (lane >> 2);
    const int r1 = r0 + 8;
    const bool p0 = r0 < n;
    const bool p1 = r1 < n;
    const float* A0 = A + (size_t)r0 * DN + (lane & 3) * 2;
    const float* A1 = A + (size_t)r1 * DN + (lane & 3) * 2;

    __syncthreads();

    float acc[16][4];
#pragma unroll
    for (int jn = 0; jn < 16; jn++)
#pragma unroll
        for (int q = 0; q < 4; q++) acc[jn][q] = 0.f;

    const int lrow = lane & 15;
    const int lcol = (lane >> 4) << 3;
    const float2 fz = make_float2(0.f, 0.f);

#pragma unroll
    for (int ks = 0; ks < 8; ks++) {
        const int k0 = ks * 16;
        // A fragment: 4 float2 direct global loads -> fp16 (single rounding)
        float2 f00 = p0 ? *reinterpret_cast<const float2*>(A0 + k0) : fz;
        float2 f10 = p1 ? *reinterpret_cast<const float2*>(A1 + k0) : fz;
        float2 f01 = p0 ? *reinterpret_cast<const float2*>(A0 + k0 + 8) : fz;
        float2 f11 = p1 ? *reinterpret_cast<const float2*>(A1 + k0 + 8) : fz;
        if (RELU) {
            f00.x = fmaxf(f00.x, 0.f); f00.y = fmaxf(f00.y, 0.f);
            f10.x = fmaxf(f10.x, 0.f); f10.y = fmaxf(f10.y, 0.f);
            f01.x = fmaxf(f01.x, 0.f); f01.y = fmaxf(f01.y, 0.f);
            f11.x = fmaxf(f11.x, 0.f); f11.y = fmaxf(f11.y, 0.f);
        }
        uint32_t ah[4];
        __half2 h;
        h = __floats2half2_rn(f00.x, f00.y); ah[0] = *reinterpret_cast<uint32_t*>(&h);
        h = __floats2half2_rn(f10.x, f10.y); ah[1] = *reinterpret_cast<uint32_t*>(&h);
        h = __floats2half2_rn(f01.x, f01.y); ah[2] = *reinterpret_cast<uint32_t*>(&h);
        h = __floats2half2_rn(f11.x, f11.y); ah[3] = *reinterpret_cast<uint32_t*>(&h);

#pragma unroll
        for (int jg = 0; jg < 8; jg++) {
            uint32_t bh[4], bl[4];
            uint32_t off = (uint32_t)(((jg * 16 + lrow) * BPAD + k0 + lcol) * 2);
            LDMATRIX_X4(bh, sbase + SMB_HI + off);
            LDMATRIX_X4(bl, sbase + SMB_LO + off);
            MMA_F16(acc[jg * 2],     ah, bh[0], bh[2]);
            MMA_F16(acc[jg * 2 + 1], ah, bh[1], bh[3]);
            MMA_F16(acc[jg * 2],     ah, bl[0], bl[2]);
            MMA_F16(acc[jg * 2 + 1], ah, bl[1], bl[3]);
        }
    }
    __syncthreads();     // done reading B smem; reuse as fp32 staging

    // --- Epilogue: stage fp32, coalesced store ---
    {
        float* stage = reinterpret_cast<float*>(smem);   // 128 x STG_STRIDE fp32
        const int trow = lane >> 2;
        const int tcol = (lane & 3) * 2;
#pragma unroll
        for (int jn = 0; jn < 16; jn++) {
            int rr = wid * 16 + trow;
            int c = jn * 8 + tcol;
            stage[rr * STG_STRIDE + c]     = acc[jn][0];
            stage[rr * STG_STRIDE + c + 1] = acc[jn][1];
            stage[(rr + 8) * STG_STRIDE + c]     = acc[jn][2];
            stage[(rr + 8) * STG_STRIDE + c + 1] = acc[jn][3];
        }
        __syncthreads();
        float4* C4 = reinterpret_cast<float4*>(C);
#pragma unroll
        for (int i = 0; i < 16; i++) {
            int f = tid + i * 256;
            int r = f >> 5;
            int c4 = f & 31;
            int gr = block_row + r;
            if (gr < n) {
                const float* sp = &stage[r * STG_STRIDE + c4 * 4];
                C4[(size_t)gr * 32 + c4] = make_float4(sp[0], sp[1], sp[2], sp[3]);
            }
        }
    }
}

// ---------------------------------------------------------------------------
// Gather (no atomics): warp per target node c, h UNSCALED:
//   out[c] = dinv[c] * ( dinv[c]*h[c] + sum_r dinv[r]*h[r] ) + b
// ---------------------------------------------------------------------------
__global__ void __launch_bounds__(256)
k_gather(const float* __restrict__ h, const float* __restrict__ dinv,
         const int* __restrict__ rowstart, const int* __restrict__ csr,
         const float* __restrict__ b, float* __restrict__ out, int n) {
    int gid = blockIdx.x * blockDim.x + threadIdx.x;
    int node = gid >> 5;
    if (node >= n) return;
    int lane = gid & 31;

    const float4* h4 = reinterpret_cast<const float4*>(h);
    float dc = __ldg(&dinv[node]);
    float4 self = __ldg(&h4[(size_t)node * 32 + lane]);
    float4 acc;
    acc.x = dc * self.x; acc.y = dc * self.y;
    acc.z = dc * self.z; acc.w = dc * self.w;

    int s = __ldg(&rowstart[node]);
    int t = __ldg(&rowstart[node + 1]);
#pragma unroll 4
    for (int j = s; j < t; j++) {
        int r = __ldg(&csr[j]);
        float dr = __ldg(&dinv[r]);
        float4 v = __ldg(&h4[(size_t)r * 32 + lane]);
        acc.x = fmaf(dr, v.x, acc.x);
        acc.y = fmaf(dr, v.y, acc.y);
        acc.z = fmaf(dr, v.z, acc.z);
        acc.w = fmaf(dr, v.w, acc.w);
    }

    float4 bv = reinterpret_cast<const float4*>(b)[lane];
    float4 o;
    o.x = fmaf(dc, acc.x, bv.x);
    o.y = fmaf(dc, acc.y, bv.y);
    o.z = fmaf(dc, acc.z, bv.z);
    o.w = fmaf(dc, acc.w, bv.w);
    reinterpret_cast<float4*>(out)[(size_t)node * 32 + lane] = o;
}

// ---------------------------------------------------------------------------
extern "C" void kernel_launch(void* const* d_in, const int* in_sizes, int n_in,
                              void* d_out, int out_size) {
    const float* x  = (const float*)d_in[0];
    const int*   ei = (const int*)d_in[1];
    const float* W1 = (const float*)d_in[2];
    const float* b1 = (const float*)d_in[3];
    const float* W2 = (const float*)d_in[4];
    const float* b2 = (const float*)d_in[5];
    float* out = (float*)d_out;

    const int n = in_sizes[0] / DN;
    const int e = in_sizes[1] / 2;
    const int* rowv = ei;
    const int* colv = ei + e;

    int *degi, *part, *bsums, *rowstart, *cursor, *csr;
    float *dinv, *buf1, *buf2;
    __half *Bhi, *Blo;
    cudaGetSymbolAddress((void**)&degi, g_degi);
    cudaGetSymbolAddress((void**)&part, g_part);
    cudaGetSymbolAddress((void**)&bsums, g_bsums);
    cudaGetSymbolAddress((void**)&rowstart, g_rowstart);
    cudaGetSymbolAddress((void**)&cursor, g_cursor);
    cudaGetSymbolAddress((void**)&csr, g_csr);
    cudaGetSymbolAddress((void**)&dinv, g_dinv);
    cudaGetSymbolAddress((void**)&buf1, g_buf1);
    cudaGetSymbolAddress((void**)&buf2, g_buf2);
    cudaGetSymbolAddress((void**)&Bhi, g_Bhi);
    cudaGetSymbolAddress((void**)&Blo, g_Blo);

    cudaFuncSetAttribute(k_gemm_mma<false>,
                         cudaFuncAttributeMaxDynamicSharedMemorySize, SM_GEMM_TOTAL);
    cudaFuncSetAttribute(k_gemm_mma<true>,
                         cudaFuncAttributeMaxDynamicSharedMemorySize, SM_GEMM_TOTAL);

    const int T = 256;
    const int nb = (n + T - 1) / T;
    const int eb = (e + T - 1) / T;
    const int eb4 = ((e + 3) / 4 + T - 1) / T;

    // W split (both layers, one launch)
    k_wsplit<<<(2 * DN * DN + T - 1) / T, T>>>(W1, W2, Bhi, Blo);

    // CSR build + dinv
    cudaMemsetAsync(degi, 0, n * sizeof(int));
    k_count_deg<<<eb4, T>>>(colv, degi, e);
    k_scan1<<<nb, T>>>(degi, part, bsums, n);
    k_scan3<<<nb, T>>>(part, bsums, degi, dinv, rowstart, cursor, n, e);
    k_fill<<<eb, T>>>(rowv, colv, cursor, csr, e);

    const int gemm_blocks = (n + 127) / 128;
    const int gather_blocks = (int)(((long long)n * 32 + T - 1) / T);

    // Layer 1
    k_gemm_mma<false><<<gemm_blocks, T, SM_GEMM_TOTAL>>>(x, Bhi, Blo, buf1, n);
    k_gather<<<gather_blocks, T>>>(buf1, dinv, rowstart, csr, b1, buf2, n);
    // Layer 2
    k_gemm_mma<true><<<gemm_blocks, T, SM_GEMM_TOTAL>>>(buf2, Bhi + DN * BPAD,
                                                        Blo + DN * BPAD, buf1, n);
    k_gather<<<gather_blocks, T>>>(buf1, dinv, rowstart, csr, b2, out, n);
}

// round 9
// speedup vs baseline: 3.0532x; 1.1675x over previous
#include <cuda_runtime.h>
#include <cuda_fp16.h>
#include <cstdint>

#define DN 128
#define N_MAX 100000
#define E_MAX 2000000
#define BPAD 136                 // padded fp16 row stride (ldmatrix conflict-free)

// ---------------------------------------------------------------------------
// Scratch (__device__ globals; no allocation allowed)
// ---------------------------------------------------------------------------
__device__ int   g_degi[N_MAX];
__device__ int   g_part[N_MAX];
__device__ int   g_bsums[512];
__device__ int   g_rowstart[N_MAX + 1];
__device__ int   g_cursor[N_MAX];
__device__ int   g_csr[E_MAX];
__device__ float g_dinv[N_MAX];
// fp16 feature buffers (h / agg), 128 halfs per node
__device__ __align__(16) __half g_hbuf1[(size_t)N_MAX * DN];
__device__ __align__(16) __half g_hbuf2[(size_t)N_MAX * DN];
// W transposed+split: B[n][k] = W[k][n], exact fp16 2-term (hi + lo)
__device__ __align__(16) __half g_Bhi[2][DN * BPAD];
__device__ __align__(16) __half g_Blo[2][DN * BPAD];

__device__ __forceinline__ uint32_t smem_to_u32(const void* p) {
    uint32_t addr;
    asm("{ .reg .u64 tmp; cvta.to.shared.u64 tmp, %1; cvt.u32.u64 %0, tmp; }"
        : "=r"(addr) : "l"(p));
    return addr;
}

#define LDMATRIX_X4(r, addr) \
    asm volatile("ldmatrix.sync.aligned.m8n8.x4.shared.b16 {%0,%1,%2,%3}, [%4];" \
                 : "=r"((r)[0]), "=r"((r)[1]), "=r"((r)[2]), "=r"((r)[3]) \
                 : "r"(addr))

#define MMA_F16(d, a, b0, b1) \
    asm volatile("mma.sync.aligned.m16n8k16.row.col.f32.f16.f16.f32 " \
                 "{%0,%1,%2,%3}, {%4,%5,%6,%7}, {%8,%9}, {%0,%1,%2,%3};" \
                 : "+f"((d)[0]), "+f"((d)[1]), "+f"((d)[2]), "+f"((d)[3]) \
                 : "r"((a)[0]), "r"((a)[1]), "r"((a)[2]), "r"((a)[3]), \
                   "r"(b0), "r"(b1))

// ---------------------------------------------------------------------------
// CSR build (by target/col node) + dinv
// ---------------------------------------------------------------------------
__global__ void k_count_deg(const int* __restrict__ col, int* __restrict__ deg, int e) {
    int i = blockIdx.x * blockDim.x + threadIdx.x;
    int base = i * 4;
    if (base + 3 < e) {
        int4 c = *reinterpret_cast<const int4*>(col + base);
        atomicAdd(&deg[c.x], 1);
        atomicAdd(&deg[c.y], 1);
        atomicAdd(&deg[c.z], 1);
        atomicAdd(&deg[c.w], 1);
    } else {
        for (int j = base; j < e; j++) atomicAdd(&deg[col[j]], 1);
    }
}

__global__ void k_scan1(const int* __restrict__ deg, int* __restrict__ part,
                        int* __restrict__ bsums, int n) {
    __shared__ int sh[256];
    int t = threadIdx.x;
    int i = blockIdx.x * 256 + t;
    int v = (i < n) ? deg[i] : 0;
    sh[t] = v;
    __syncthreads();
#pragma unroll
    for (int off = 1; off < 256; off <<= 1) {
        int add = (t >= off) ? sh[t - off] : 0;
        __syncthreads();
        sh[t] += add;
        __syncthreads();
    }
    if (i < n) part[i] = sh[t] - v;
    if (t == 255) bsums[blockIdx.x] = sh[255];
}

__global__ void k_scan3(const int* __restrict__ part, const int* __restrict__ bsums,
                        const int* __restrict__ deg, float* __restrict__ dinv,
                        int* __restrict__ rowstart, int* __restrict__ cursor,
                        int n, int e) {
    __shared__ int sred[256];
    int t = threadIdx.x;
    int accum = 0;
    for (int j = t; j < (int)blockIdx.x; j += 256) accum += bsums[j];
    sred[t] = accum;
    __syncthreads();
#pragma unroll
    for (int off = 128; off > 0; off >>= 1) {
        if (t < off) sred[t] += sred[t + off];
        __syncthreads();
    }
    int base = sred[0];

    int i = blockIdx.x * 256 + t;
    if (i < n) {
        int v = part[i] + base;
        rowstart[i] = v;
        cursor[i] = v;
        dinv[i] = rsqrtf((float)deg[i] + 1.0f);
    }
    if (i == 0 && blockIdx.x == 0) rowstart[n] = e;
}

__global__ void k_fill(const int* __restrict__ rowv, const int* __restrict__ colv,
                       int* __restrict__ cursor, int* __restrict__ csr, int e) {
    int i = blockIdx.x * blockDim.x + threadIdx.x;
    if (i < e) {
        int pos = atomicAdd(&cursor[colv[i]], 1);
        csr[pos] = rowv[i];
    }
}

// ---------------------------------------------------------------------------
// W split (both layers, one launch): B[n][k] = W[k][n] -> exact fp16 hi/lo
// ---------------------------------------------------------------------------
__global__ void k_wsplit(const float* __restrict__ W1, const float* __restrict__ W2,
                         __half* __restrict__ Bhi, __half* __restrict__ Blo) {
    int gi = blockIdx.x * blockDim.x + threadIdx.x;
    if (gi >= 2 * DN * DN) return;
    int layer = gi >> 14;
    int i = gi & (DN * DN - 1);
    const float* W = layer ? W2 : W1;
    int nrow = i & 127;
    int k = i >> 7;
    float w = W[k * DN + nrow];
    __half hi = __float2half_rn(w);
    __half lo = __float2half_rn(w - __half2float(hi));
    Bhi[layer * DN * BPAD + nrow * BPAD + k] = hi;
    Blo[layer * DN * BPAD + nrow * BPAD + k] = lo;
}

// ---------------------------------------------------------------------------
// mma.sync GEMM: Cfp16 = act(A) @ W, fp16 2-term W split.
// IN16: A is fp16 (loaded straight into fragments); else fp32 + convert.
// Output always fp16. 256 thr = 8 warps; warp w owns rows [w*16,w*16+16).
// Smem = B hi/lo (68 KB) -> 2 CTAs/SM.
// ---------------------------------------------------------------------------
#define SMB_HI 0
#define SMB_LO (DN * BPAD * 2)                 // 34816
#define SM_GEMM_TOTAL (2 * DN * BPAD * 2)      // 69632
#define STG_STRIDE 132

template <bool RELU, bool IN16>
__global__ void __launch_bounds__(256, 2)
k_gemm_mma(const void* __restrict__ Ain, const __half* __restrict__ Bhi,
           const __half* __restrict__ Blo, __half* __restrict__ C, int n) {
    extern __shared__ __align__(16) char smem[];
    const uint32_t sbase = smem_to_u32(smem);
    const int tid = threadIdx.x;
    const int wid = tid >> 5;
    const int lane = tid & 31;
    const int block_row = blockIdx.x * 128;

    // --- B copy (pre-split, padded) ---
    {
        const uint4* srcH = reinterpret_cast<const uint4*>(Bhi);
        const uint4* srcL = reinterpret_cast<const uint4*>(Blo);
        uint4* dstH = reinterpret_cast<uint4*>(smem + SMB_HI);
        uint4* dstL = reinterpret_cast<uint4*>(smem + SMB_LO);
#pragma unroll
        for (int i = 0; i < 9; i++) {
            int f = tid + i * 256;
            if (f < DN * BPAD / 8) {
                dstH[f] = __ldg(&srcH[f]);
                dstL[f] = __ldg(&srcL[f]);
            }
        }
    }

    const int r0 = block_row + wid * 16 + (lane >> 2);
    const int r1 = r0 + 8;
    const bool p0 = r0 < n;
    const bool p1 = r1 < n;
    const int coff = (lane & 3) * 2;

    __syncthreads();

    float acc[16][4];
#pragma unroll
    for (int jn = 0; jn < 16; jn++)
#pragma unroll
        for (int q = 0; q < 4; q++) acc[jn][q] = 0.f;

    const int lrow = lane & 15;
    const int lcol = (lane >> 4) << 3;

#pragma unroll
    for (int ks = 0; ks < 8; ks++) {
        const int k0 = ks * 16;
        uint32_t ah[4];
        if (IN16) {
            const __half* A = reinterpret_cast<const __half*>(Ain);
            const __half* A0 = A + (size_t)r0 * DN + coff;
            const __half* A1 = A + (size_t)r1 * DN + coff;
            __half2 z2 = __float2half2_rn(0.f);
            __half2 v0 = p0 ? *reinterpret_cast<const __half2*>(A0 + k0) : z2;
            __half2 v1 = p1 ? *reinterpret_cast<const __half2*>(A1 + k0) : z2;
            __half2 v2 = p0 ? *reinterpret_cast<const __half2*>(A0 + k0 + 8) : z2;
            __half2 v3 = p1 ? *reinterpret_cast<const __half2*>(A1 + k0 + 8) : z2;
            if (RELU) {
                v0 = __hmax2(v0, z2); v1 = __hmax2(v1, z2);
                v2 = __hmax2(v2, z2); v3 = __hmax2(v3, z2);
            }
            ah[0] = *reinterpret_cast<uint32_t*>(&v0);
            ah[1] = *reinterpret_cast<uint32_t*>(&v1);
            ah[2] = *reinterpret_cast<uint32_t*>(&v2);
            ah[3] = *reinterpret_cast<uint32_t*>(&v3);
        } else {
            const float* A = reinterpret_cast<const float*>(Ain);
            const float* A0 = A + (size_t)r0 * DN + coff;
            const float* A1 = A + (size_t)r1 * DN + coff;
            const float2 fz = make_float2(0.f, 0.f);
            float2 f00 = p0 ? *reinterpret_cast<const float2*>(A0 + k0) : fz;
            float2 f10 = p1 ? *reinterpret_cast<const float2*>(A1 + k0) : fz;
            float2 f01 = p0 ? *reinterpret_cast<const float2*>(A0 + k0 + 8) : fz;
            float2 f11 = p1 ? *reinterpret_cast<const float2*>(A1 + k0 + 8) : fz;
            if (RELU) {
                f00.x = fmaxf(f00.x, 0.f); f00.y = fmaxf(f00.y, 0.f);
                f10.x = fmaxf(f10.x, 0.f); f10.y = fmaxf(f10.y, 0.f);
                f01.x = fmaxf(f01.x, 0.f); f01.y = fmaxf(f01.y, 0.f);
                f11.x = fmaxf(f11.x, 0.f); f11.y = fmaxf(f11.y, 0.f);
            }
            __half2 h;
            h = __floats2half2_rn(f00.x, f00.y); ah[0] = *reinterpret_cast<uint32_t*>(&h);
            h = __floats2half2_rn(f10.x, f10.y); ah[1] = *reinterpret_cast<uint32_t*>(&h);
            h = __floats2half2_rn(f01.x, f01.y); ah[2] = *reinterpret_cast<uint32_t*>(&h);
            h = __floats2half2_rn(f11.x, f11.y); ah[3] = *reinterpret_cast<uint32_t*>(&h);
        }

#pragma unroll
        for (int jg = 0; jg < 8; jg++) {
            uint32_t bh[4], bl[4];
            uint32_t off = (uint32_t)(((jg * 16 + lrow) * BPAD + k0 + lcol) * 2);
            LDMATRIX_X4(bh, sbase + SMB_HI + off);
            LDMATRIX_X4(bl, sbase + SMB_LO + off);
            MMA_F16(acc[jg * 2],     ah, bh[0], bh[2]);
            MMA_F16(acc[jg * 2 + 1], ah, bh[1], bh[3]);
            MMA_F16(acc[jg * 2],     ah, bl[0], bl[2]);
            MMA_F16(acc[jg * 2 + 1], ah, bl[1], bl[3]);
        }
    }
    __syncthreads();     // done reading B smem; reuse as fp32 staging

    // --- Epilogue: stage fp32, convert + coalesced fp16 store ---
    {
        float* stage = reinterpret_cast<float*>(smem);   // 128 x STG_STRIDE fp32
        const int trow = lane >> 2;
        const int tcol = (lane & 3) * 2;
#pragma unroll
        for (int jn = 0; jn < 16; jn++) {
            int rr = wid * 16 + trow;
            int c = jn * 8 + tcol;
            stage[rr * STG_STRIDE + c]     = acc[jn][0];
            stage[rr * STG_STRIDE + c + 1] = acc[jn][1];
            stage[(rr + 8) * STG_STRIDE + c]     = acc[jn][2];
            stage[(rr + 8) * STG_STRIDE + c + 1] = acc[jn][3];
        }
        __syncthreads();
        uint2* C2 = reinterpret_cast<uint2*>(C);        // 4 halfs per uint2
#pragma unroll
        for (int i = 0; i < 16; i++) {
            int f = tid + i * 256;                      // 4096 uint2
            int r = f >> 5;                             // 32 uint2 per row
            int c4 = f & 31;
            int gr = block_row + r;
            if (gr < n) {
                const float* sp = &stage[r * STG_STRIDE + c4 * 4];
                __half2 a = __floats2half2_rn(sp[0], sp[1]);
                __half2 b = __floats2half2_rn(sp[2], sp[3]);
                C2[(size_t)gr * 32 + c4] =
                    make_uint2(*reinterpret_cast<uint32_t*>(&a),
                               *reinterpret_cast<uint32_t*>(&b));
            }
        }
    }
}

// ---------------------------------------------------------------------------
// Gather (no atomics): warp per target node c, h fp16, fp32 accumulate:
//   out[c] = dinv[c] * ( dinv[c]*h[c] + sum_r dinv[r]*h[r] ) + b
// OUT16: write fp16 (intermediate agg); else fp32 (final output).
// Lane handles 4 feature columns (lane*4 .. lane*4+3).
// ---------------------------------------------------------------------------
template <bool OUT16>
__global__ void __launch_bounds__(256)
k_gather(const __half* __restrict__ h, const float* __restrict__ dinv,
         const int* __restrict__ rowstart, const int* __restrict__ csr,
         const float* __restrict__ b, void* __restrict__ outp, int n) {
    int gid = blockIdx.x * blockDim.x + threadIdx.x;
    int node = gid >> 5;
    if (node >= n) return;
    int lane = gid & 31;

    const uint2* h2 = reinterpret_cast<const uint2*>(h);   // 4 halfs per uint2
    float dc = __ldg(&dinv[node]);

    uint2 sv = __ldg(&h2[(size_t)node * 32 + lane]);
    __half2 s01 = *reinterpret_cast<__half2*>(&sv.x);
    __half2 s23 = *reinterpret_cast<__half2*>(&sv.y);
    float2 f01 = __half22float2(s01);
    float2 f23 = __half22float2(s23);
    float4 acc;
    acc.x = dc * f01.x; acc.y = dc * f01.y;
    acc.z = dc * f23.x; acc.w = dc * f23.y;

    int s = __ldg(&rowstart[node]);
    int t = __ldg(&rowstart[node + 1]);
#pragma unroll 4
    for (int j = s; j < t; j++) {
        int r = __ldg(&csr[j]);
        float dr = __ldg(&dinv[r]);
        uint2 v = __ldg(&h2[(size_t)r * 32 + lane]);
        __half2 v01 = *reinterpret_cast<__half2*>(&v.x);
        __half2 v23 = *reinterpret_cast<__half2*>(&v.y);
        float2 g01 = __half22float2(v01);
        float2 g23 = __half22float2(v23);
        acc.x = fmaf(dr, g01.x, acc.x);
        acc.y = fmaf(dr, g01.y, acc.y);
        acc.z = fmaf(dr, g23.x, acc.z);
        acc.w = fmaf(dr, g23.y, acc.w);
    }

    float4 bv = reinterpret_cast<const float4*>(b)[lane];
    float4 o;
    o.x = fmaf(dc, acc.x, bv.x);
    o.y = fmaf(dc, acc.y, bv.y);
    o.z = fmaf(dc, acc.z, bv.z);
    o.w = fmaf(dc, acc.w, bv.w);

    if (OUT16) {
        __half2 a = __floats2half2_rn(o.x, o.y);
        __half2 c = __floats2half2_rn(o.z, o.w);
        reinterpret_cast<uint2*>(outp)[(size_t)node * 32 + lane] =
            make_uint2(*reinterpret_cast<uint32_t*>(&a),
                       *reinterpret_cast<uint32_t*>(&c));
    } else {
        reinterpret_cast<float4*>(outp)[(size_t)node * 32 + lane] = o;
    }
}

// ---------------------------------------------------------------------------
extern "C" void kernel_launch(void* const* d_in, const int* in_sizes, int n_in,
                              void* d_out, int out_size) {
    const float* x  = (const float*)d_in[0];
    const int*   ei = (const int*)d_in[1];
    const float* W1 = (const float*)d_in[2];
    const float* b1 = (const float*)d_in[3];
    const float* W2 = (const float*)d_in[4];
    const float* b2 = (const float*)d_in[5];
    float* out = (float*)d_out;

    const int n = in_sizes[0] / DN;
    const int e = in_sizes[1] / 2;
    const int* rowv = ei;
    const int* colv = ei + e;

    int *degi, *part, *bsums, *rowstart, *cursor, *csr;
    float *dinv;
    __half *hbuf1, *hbuf2, *Bhi, *Blo;
    cudaGetSymbolAddress((void**)&degi, g_degi);
    cudaGetSymbolAddress((void**)&part, g_part);
    cudaGetSymbolAddress((void**)&bsums, g_bsums);
    cudaGetSymbolAddress((void**)&rowstart, g_rowstart);
    cudaGetSymbolAddress((void**)&cursor, g_cursor);
    cudaGetSymbolAddress((void**)&csr, g_csr);
    cudaGetSymbolAddress((void**)&dinv, g_dinv);
    cudaGetSymbolAddress((void**)&hbuf1, g_hbuf1);
    cudaGetSymbolAddress((void**)&hbuf2, g_hbuf2);
    cudaGetSymbolAddress((void**)&Bhi, g_Bhi);
    cudaGetSymbolAddress((void**)&Blo, g_Blo);

    cudaFuncSetAttribute(k_gemm_mma<false, false>,
                         cudaFuncAttributeMaxDynamicSharedMemorySize, SM_GEMM_TOTAL);
    cudaFuncSetAttribute(k_gemm_mma<true, true>,
                         cudaFuncAttributeMaxDynamicSharedMemorySize, SM_GEMM_TOTAL);

    const int T = 256;
    const int nb = (n + T - 1) / T;
    const int eb = (e + T - 1) / T;
    const int eb4 = ((e + 3) / 4 + T - 1) / T;

    // W split (both layers, one launch)
    k_wsplit<<<(2 * DN * DN + T - 1) / T, T>>>(W1, W2, Bhi, Blo);

    // CSR build + dinv
    cudaMemsetAsync(degi, 0, n * sizeof(int));
    k_count_deg<<<eb4, T>>>(colv, degi, e);
    k_scan1<<<nb, T>>>(degi, part, bsums, n);
    k_scan3<<<nb, T>>>(part, bsums, degi, dinv, rowstart, cursor, n, e);
    k_fill<<<eb, T>>>(rowv, colv, cursor, csr, e);

    const int gemm_blocks = (n + 127) / 128;
    const int gather_blocks = (int)(((long long)n * 32 + T - 1) / T);

    // Layer 1: x (fp32) -> h1 (fp16) -> agg1 (fp16)
    k_gemm_mma<false, false><<<gemm_blocks, T, SM_GEMM_TOTAL>>>(x, Bhi, Blo, hbuf1, n);
    k_gather<true><<<gather_blocks, T>>>(hbuf1, dinv, rowstart, csr, b1, hbuf2, n);
    // Layer 2: relu(agg1) (fp16) -> h2 (fp16) -> out (fp32)
    k_gemm_mma<true, true><<<gemm_blocks, T, SM_GEMM_TOTAL>>>(hbuf2, Bhi + DN * BPAD,
                                                              Blo + DN * BPAD, hbuf1, n);
    k_gather<false><<<gather_blocks, T>>>(hbuf1, dinv, rowstart, csr, b2, out, n);
}

// round 10
// speedup vs baseline: 3.3028x; 1.0817x over previous
#include <cuda_runtime.h>
#include <cuda_fp16.h>
#include <cstdint>

#define DN 128
#define N_MAX 100000
#define E_MAX 2000000
#define BPAD 136                 // padded fp16 row stride (ldmatrix conflict-free)

// ---------------------------------------------------------------------------
// Scratch (__device__ globals; no allocation allowed)
// ---------------------------------------------------------------------------
__device__ int   g_degi[N_MAX];
__device__ int   g_part[N_MAX];
__device__ int   g_bsums[512];
__device__ int   g_rowstart[N_MAX + 1];
__device__ int   g_cursor[N_MAX];
__device__ int   g_csr[E_MAX];
__device__ float g_dinv[N_MAX];
// fp16 feature buffers (dinv-scaled h / agg), 128 halfs per node
__device__ __align__(16) __half g_hbuf1[(size_t)N_MAX * DN];
__device__ __align__(16) __half g_hbuf2[(size_t)N_MAX * DN];
// W transposed: B[n][k] = W[k][n], fp16, padded [n][BPAD]; 2 layers
__device__ __align__(16) __half g_B[2][DN * BPAD];

__device__ __forceinline__ uint32_t smem_to_u32(const void* p) {
    uint32_t addr;
    asm("{ .reg .u64 tmp; cvta.to.shared.u64 tmp, %1; cvt.u32.u64 %0, tmp; }"
        : "=r"(addr) : "l"(p));
    return addr;
}

#define LDMATRIX_X4(r, addr) \
    asm volatile("ldmatrix.sync.aligned.m8n8.x4.shared.b16 {%0,%1,%2,%3}, [%4];" \
                 : "=r"((r)[0]), "=r"((r)[1]), "=r"((r)[2]), "=r"((r)[3]) \
                 : "r"(addr))

#define MMA_F16(d, a, b0, b1) \
    asm volatile("mma.sync.aligned.m16n8k16.row.col.f32.f16.f16.f32 " \
                 "{%0,%1,%2,%3}, {%4,%5,%6,%7}, {%8,%9}, {%0,%1,%2,%3};" \
                 : "+f"((d)[0]), "+f"((d)[1]), "+f"((d)[2]), "+f"((d)[3]) \
                 : "r"((a)[0]), "r"((a)[1]), "r"((a)[2]), "r"((a)[3]), \
                   "r"(b0), "r"(b1))

// ---------------------------------------------------------------------------
// CSR build (by target/col node) + dinv
// ---------------------------------------------------------------------------
__global__ void k_count_deg(const int* __restrict__ col, int* __restrict__ deg, int e) {
    int i = blockIdx.x * blockDim.x + threadIdx.x;
    int base = i * 4;
    if (base + 3 < e) {
        int4 c = *reinterpret_cast<const int4*>(col + base);
        atomicAdd(&deg[c.x], 1);
        atomicAdd(&deg[c.y], 1);
        atomicAdd(&deg[c.z], 1);
        atomicAdd(&deg[c.w], 1);
    } else {
        for (int j = base; j < e; j++) atomicAdd(&deg[col[j]], 1);
    }
}

__global__ void k_scan1(const int* __restrict__ deg, int* __restrict__ part,
                        int* __restrict__ bsums, int n) {
    __shared__ int sh[256];
    int t = threadIdx.x;
    int i = blockIdx.x * 256 + t;
    int v = (i < n) ? deg[i] : 0;
    sh[t] = v;
    __syncthreads();
#pragma unroll
    for (int off = 1; off < 256; off <<= 1) {
        int add = (t >= off) ? sh[t - off] : 0;
        __syncthreads();
        sh[t] += add;
        __syncthreads();
    }
    if (i < n) part[i] = sh[t] - v;
    if (t == 255) bsums[blockIdx.x] = sh[255];
}

__global__ void k_scan3(const int* __restrict__ part, const int* __restrict__ bsums,
                        const int* __restrict__ deg, float* __restrict__ dinv,
                        int* __restrict__ rowstart, int* __restrict__ cursor,
                        int n, int e) {
    __shared__ int sred[256];
    int t = threadIdx.x;
    int accum = 0;
    for (int j = t; j < (int)blockIdx.x; j += 256) accum += bsums[j];
    sred[t] = accum;
    __syncthreads();
#pragma unroll
    for (int off = 128; off > 0; off >>= 1) {
        if (t < off) sred[t] += sred[t + off];
        __syncthreads();
    }
    int base = sred[0];

    int i = blockIdx.x * 256 + t;
    if (i < n) {
        int v = part[i] + base;
        rowstart[i] = v;
        cursor[i] = v;
        dinv[i] = rsqrtf((float)deg[i] + 1.0f);
    }
    if (i == 0 && blockIdx.x == 0) rowstart[n] = e;
}

__global__ void k_fill(const int* __restrict__ rowv, const int* __restrict__ colv,
                       int* __restrict__ cursor, int* __restrict__ csr, int e) {
    int i = blockIdx.x * blockDim.x + threadIdx.x;
    if (i < e) {
        int pos = atomicAdd(&cursor[colv[i]], 1);
        csr[pos] = rowv[i];
    }
}

// ---------------------------------------------------------------------------
// W convert (both layers, one launch): B[n][k] = W[k][n] fp16, padded
// ---------------------------------------------------------------------------
__global__ void k_wconv(const float* __restrict__ W1, const float* __restrict__ W2,
                        __half* __restrict__ B) {
    int gi = blockIdx.x * blockDim.x + threadIdx.x;
    if (gi >= 2 * DN * DN) return;
    int layer = gi >> 14;
    int i = gi & (DN * DN - 1);
    const float* W = layer ? W2 : W1;
    int nrow = i & 127;
    int k = i >> 7;
    B[layer * DN * BPAD + nrow * BPAD + k] = __float2half_rn(W[k * DN + nrow]);
}

// ---------------------------------------------------------------------------
// mma.sync GEMM: C_fp16[i,:] = dinv[i] * (act(A[i,:]) @ W)
// Single fp16 W. 256 thr = 8 warps; warp w owns rows [w*16, w*16+16).
// Smem = B (34 KB) + reused fp32 staging -> 2 CTAs/SM.
// ---------------------------------------------------------------------------
#define SMB 0
#define SM_B_BYTES (DN * BPAD * 2)             // 34816
#define STG_STRIDE 132
#define SM_STG_BYTES (DN * STG_STRIDE * 4)     // 67584
#define SM_GEMM_TOTAL (SM_STG_BYTES)           // staging > B; B overlaps staging
// NOTE: B lives at [0, 34816); staging needs all 67584 bytes and is only used
// AFTER the last B read (post-__syncthreads). Total allocation = 67584.

template <bool RELU, bool IN16>
__global__ void __launch_bounds__(256, 2)
k_gemm_mma(const void* __restrict__ Ain, const __half* __restrict__ Bg,
           const float* __restrict__ dinv, __half* __restrict__ C, int n) {
    extern __shared__ __align__(16) char smem[];
    const uint32_t sbase = smem_to_u32(smem);
    const int tid = threadIdx.x;
    const int wid = tid >> 5;
    const int lane = tid & 31;
    const int block_row = blockIdx.x * 128;

    // --- B copy (padded fp16, 34816 B) ---
    {
        const uint4* src = reinterpret_cast<const uint4*>(Bg);
        uint4* dst = reinterpret_cast<uint4*>(smem + SMB);
#pragma unroll
        for (int i = 0; i < 9; i++) {
            int f = tid + i * 256;
            if (f < DN * BPAD / 8) dst[f] = __ldg(&src[f]);
        }
    }

    const int r0 = block_row + wid * 16 + (lane >> 2);
    const int r1 = r0 + 8;
    const bool p0 = r0 < n;
    const bool p1 = r1 < n;
    const int coff = (lane & 3) * 2;

    __syncthreads();

    float acc[16][4];
#pragma unroll
    for (int jn = 0; jn < 16; jn++)
#pragma unroll
        for (int q = 0; q < 4; q++) acc[jn][q] = 0.f;

    const int lrow = lane & 15;
    const int lcol = (lane >> 4) << 3;

#pragma unroll
    for (int ks = 0; ks < 8; ks++) {
        const int k0 = ks * 16;
        uint32_t ah[4];
        if (IN16) {
            const __half* A = reinterpret_cast<const __half*>(Ain);
            const __half* A0 = A + (size_t)r0 * DN + coff;
            const __half* A1 = A + (size_t)r1 * DN + coff;
            __half2 z2 = __float2half2_rn(0.f);
            __half2 v0 = p0 ? *reinterpret_cast<const __half2*>(A0 + k0) : z2;
            __half2 v1 = p1 ? *reinterpret_cast<const __half2*>(A1 + k0) : z2;
            __half2 v2 = p0 ? *reinterpret_cast<const __half2*>(A0 + k0 + 8) : z2;
            __half2 v3 = p1 ? *reinterpret_cast<const __half2*>(A1 + k0 + 8) : z2;
            if (RELU) {
                v0 = __hmax2(v0, z2); v1 = __hmax2(v1, z2);
                v2 = __hmax2(v2, z2); v3 = __hmax2(v3, z2);
            }
            ah[0] = *reinterpret_cast<uint32_t*>(&v0);
            ah[1] = *reinterpret_cast<uint32_t*>(&v1);
            ah[2] = *reinterpret_cast<uint32_t*>(&v2);
            ah[3] = *reinterpret_cast<uint32_t*>(&v3);
        } else {
            const float* A = reinterpret_cast<const float*>(Ain);
            const float* A0 = A + (size_t)r0 * DN + coff;
            const float* A1 = A + (size_t)r1 * DN + coff;
            const float2 fz = make_float2(0.f, 0.f);
            float2 f00 = p0 ? *reinterpret_cast<const float2*>(A0 + k0) : fz;
            float2 f10 = p1 ? *reinterpret_cast<const float2*>(A1 + k0) : fz;
            float2 f01 = p0 ? *reinterpret_cast<const float2*>(A0 + k0 + 8) : fz;
            float2 f11 = p1 ? *reinterpret_cast<const float2*>(A1 + k0 + 8) : fz;
            if (RELU) {
                f00.x = fmaxf(f00.x, 0.f); f00.y = fmaxf(f00.y, 0.f);
                f10.x = fmaxf(f10.x, 0.f); f10.y = fmaxf(f10.y, 0.f);
                f01.x = fmaxf(f01.x, 0.f); f01.y = fmaxf(f01.y, 0.f);
                f11.x = fmaxf(f11.x, 0.f); f11.y = fmaxf(f11.y, 0.f);
            }
            __half2 h;
            h = __floats2half2_rn(f00.x, f00.y); ah[0] = *reinterpret_cast<uint32_t*>(&h);
            h = __floats2half2_rn(f10.x, f10.y); ah[1] = *reinterpret_cast<uint32_t*>(&h);
            h = __floats2half2_rn(f01.x, f01.y); ah[2] = *reinterpret_cast<uint32_t*>(&h);
            h = __floats2half2_rn(f11.x, f11.y); ah[3] = *reinterpret_cast<uint32_t*>(&h);
        }

#pragma unroll
        for (int jg = 0; jg < 8; jg++) {
            uint32_t bh[4];
            uint32_t off = (uint32_t)(((jg * 16 + lrow) * BPAD + k0 + lcol) * 2);
            LDMATRIX_X4(bh, sbase + SMB + off);
            MMA_F16(acc[jg * 2],     ah, bh[0], bh[2]);
            MMA_F16(acc[jg * 2 + 1], ah, bh[1], bh[3]);
        }
    }
    __syncthreads();     // done reading B smem; reuse as fp32 staging

    // --- Epilogue: stage fp32, dinv-scale, coalesced fp16 store ---
    {
        float* stage = reinterpret_cast<float*>(smem);   // 128 x STG_STRIDE fp32
        const int trow = lane >> 2;
        const int tcol = (lane & 3) * 2;
#pragma unroll
        for (int jn = 0; jn < 16; jn++) {
            int rr = wid * 16 + trow;
            int c = jn * 8 + tcol;
            stage[rr * STG_STRIDE + c]     = acc[jn][0];
            stage[rr * STG_STRIDE + c + 1] = acc[jn][1];
            stage[(rr + 8) * STG_STRIDE + c]     = acc[jn][2];
            stage[(rr + 8) * STG_STRIDE + c + 1] = acc[jn][3];
        }
        __syncthreads();
        uint2* C2 = reinterpret_cast<uint2*>(C);        // 4 halfs per uint2
#pragma unroll
        for (int i = 0; i < 16; i++) {
            int f = tid + i * 256;
            int r = f >> 5;
            int c4 = f & 31;
            int gr = block_row + r;
            if (gr < n) {
                float s = __ldg(&dinv[gr]);
                const float* sp = &stage[r * STG_STRIDE + c4 * 4];
                __half2 a = __floats2half2_rn(s * sp[0], s * sp[1]);
                __half2 b = __floats2half2_rn(s * sp[2], s * sp[3]);
                C2[(size_t)gr * 32 + c4] =
                    make_uint2(*reinterpret_cast<uint32_t*>(&a),
                               *reinterpret_cast<uint32_t*>(&b));
            }
        }
    }
}

// ---------------------------------------------------------------------------
// Gather (no atomics): warp per target node c, h' = dinv-scaled fp16:
//   out[c] = dinv[c] * ( h'[c] + sum_r h'[r] ) + b
// OUT16: fp16 out (intermediate); else fp32 (final).
// ---------------------------------------------------------------------------
template <bool OUT16>
__global__ void __launch_bounds__(256)
k_gather(const __half* __restrict__ h, const float* __restrict__ dinv,
         const int* __restrict__ rowstart, const int* __restrict__ csr,
         const float* __restrict__ b, void* __restrict__ outp, int n) {
    int gid = blockIdx.x * blockDim.x + threadIdx.x;
    int node = gid >> 5;
    if (node >= n) return;
    int lane = gid & 31;

    const uint2* h2 = reinterpret_cast<const uint2*>(h);   // 4 halfs per uint2

    uint2 sv = __ldg(&h2[(size_t)node * 32 + lane]);
    float2 f01 = __half22float2(*reinterpret_cast<__half2*>(&sv.x));
    float2 f23 = __half22float2(*reinterpret_cast<__half2*>(&sv.y));
    float4 acc = make_float4(f01.x, f01.y, f23.x, f23.y);

    int s = __ldg(&rowstart[node]);
    int t = __ldg(&rowstart[node + 1]);
    int j = s;
    // unroll-by-2 for MLP
    for (; j + 1 < t; j += 2) {
        int ra = __ldg(&csr[j]);
        int rb = __ldg(&csr[j + 1]);
        uint2 va = __ldg(&h2[(size_t)ra * 32 + lane]);
        uint2 vb = __ldg(&h2[(size_t)rb * 32 + lane]);
        float2 a01 = __half22float2(*reinterpret_cast<__half2*>(&va.x));
        float2 a23 = __half22float2(*reinterpret_cast<__half2*>(&va.y));
        float2 b01 = __half22float2(*reinterpret_cast<__half2*>(&vb.x));
        float2 b23 = __half22float2(*reinterpret_cast<__half2*>(&vb.y));
        acc.x += a01.x + b01.x;
        acc.y += a01.y + b01.y;
        acc.z += a23.x + b23.x;
        acc.w += a23.y + b23.y;
    }
    if (j < t) {
        int r = __ldg(&csr[j]);
        uint2 v = __ldg(&h2[(size_t)r * 32 + lane]);
        float2 g01 = __half22float2(*reinterpret_cast<__half2*>(&v.x));
        float2 g23 = __half22float2(*reinterpret_cast<__half2*>(&v.y));
        acc.x += g01.x; acc.y += g01.y;
        acc.z += g23.x; acc.w += g23.y;
    }

    float dc = __ldg(&dinv[node]);
    float4 bv = reinterpret_cast<const float4*>(b)[lane];
    float4 o;
    o.x = fmaf(dc, acc.x, bv.x);
    o.y = fmaf(dc, acc.y, bv.y);
    o.z = fmaf(dc, acc.z, bv.z);
    o.w = fmaf(dc, acc.w, bv.w);

    if (OUT16) {
        __half2 a = __floats2half2_rn(o.x, o.y);
        __half2 c = __floats2half2_rn(o.z, o.w);
        reinterpret_cast<uint2*>(outp)[(size_t)node * 32 + lane] =
            make_uint2(*reinterpret_cast<uint32_t*>(&a),
                       *reinterpret_cast<uint32_t*>(&c));
    } else {
        reinterpret_cast<float4*>(outp)[(size_t)node * 32 + lane] = o;
    }
}

// ---------------------------------------------------------------------------
extern "C" void kernel_launch(void* const* d_in, const int* in_sizes, int n_in,
                              void* d_out, int out_size) {
    const float* x  = (const float*)d_in[0];
    const int*   ei = (const int*)d_in[1];
    const float* W1 = (const float*)d_in[2];
    const float* b1 = (const float*)d_in[3];
    const float* W2 = (const float*)d_in[4];
    const float* b2 = (const float*)d_in[5];
    float* out = (float*)d_out;

    const int n = in_sizes[0] / DN;
    const int e = in_sizes[1] / 2;
    const int* rowv = ei;
    const int* colv = ei + e;

    int *degi, *part, *bsums, *rowstart, *cursor, *csr;
    float *dinv;
    __half *hbuf1, *hbuf2, *B;
    cudaGetSymbolAddress((void**)&degi, g_degi);
    cudaGetSymbolAddress((void**)&part, g_part);
    cudaGetSymbolAddress((void**)&bsums, g_bsums);
    cudaGetSymbolAddress((void**)&rowstart, g_rowstart);
    cudaGetSymbolAddress((void**)&cursor, g_cursor);
    cudaGetSymbolAddress((void**)&csr, g_csr);
    cudaGetSymbolAddress((void**)&dinv, g_dinv);
    cudaGetSymbolAddress((void**)&hbuf1, g_hbuf1);
    cudaGetSymbolAddress((void**)&hbuf2, g_hbuf2);
    cudaGetSymbolAddress((void**)&B, g_B);

    cudaFuncSetAttribute(k_gemm_mma<false, false>,
                         cudaFuncAttributeMaxDynamicSharedMemorySize, SM_GEMM_TOTAL);
    cudaFuncSetAttribute(k_gemm_mma<true, true>,
                         cudaFuncAttributeMaxDynamicSharedMemorySize, SM_GEMM_TOTAL);

    const int T = 256;
    const int nb = (n + T - 1) / T;
    const int eb = (e + T - 1) / T;
    const int eb4 = ((e + 3) / 4 + T - 1) / T;

    const int gemm_blocks = (n + 127) / 128;
    const int gather_blocks = (int)(((long long)n * 32 + T - 1) / T);

    // Launch order chosen so GEMM-1 is ncu's profiled launch (-s 5):
    // 0 wconv, 1 memset, 2 count, 3 scan1, 4 scan3, 5 GEMM-1, then fill...
    k_wconv<<<(2 * DN * DN + T - 1) / T, T>>>(W1, W2, B);
    cudaMemsetAsync(degi, 0, n * sizeof(int));
    k_count_deg<<<eb4, T>>>(colv, degi, e);
    k_scan1<<<nb, T>>>(degi, part, bsums, n);
    k_scan3<<<nb, T>>>(part, bsums, degi, dinv, rowstart, cursor, n, e);

    // Layer 1 GEMM (needs dinv from scan3; not CSR)
    k_gemm_mma<false, false><<<gemm_blocks, T, SM_GEMM_TOTAL>>>(x, B, dinv, hbuf1, n);

    // CSR fill (must precede gather-1)
    k_fill<<<eb, T>>>(rowv, colv, cursor, csr, e);

    k_gather<true><<<gather_blocks, T>>>(hbuf1, dinv, rowstart, csr, b1, hbuf2, n);
    // Layer 2
    k_gemm_mma<true, true><<<gemm_blocks, T, SM_GEMM_TOTAL>>>(hbuf2, B + DN * BPAD,
                                                              dinv, hbuf1, n);
    k_gather<false><<<gather_blocks, T>>>(hbuf1, dinv, rowstart, csr, b2, out, n);
}